// round 8
// baseline (speedup 1.0000x reference)
#include <cuda_runtime.h>
#include <cstdint>
#include <math.h>

// ---------------- problem constants ----------------
#define NNODE 2048
#define NEDGE 4096
#define LF    49
#define LR    16
#define MMID  25
#define NYR   3
#define CCH   128
#define HID   128
#define XLC   (LF*CCH)      // 6272
#define FEATW 2064          // 16*129
#define MSGW  2048          // 16*128
#define TPAD  1280          // padded 1225
#define KCG   64            // padded 49

// ---------------- device scratch ----------------
__device__ __align__(16) float g_WdT  [128*128];
__device__ __align__(16) float g_Wn1aT[128*FEATW];
__device__ __align__(16) float g_Wn1bT[2048*128];
__device__ __align__(16) float g_Wn2aT[128*FEATW];
__device__ __align__(16) float g_Wn2bT[2048*128];
__device__ __align__(16) float g_Wp1T [128*2048];
__device__ __align__(16) float g_Wp2T [2048*128];
__device__ __align__(16) float g_Wc1T [TPAD*KCG];
__device__ __align__(16) float g_Wc2T [TPAD*KCG];
__device__ __align__(16) float g_Wc3T [TPAD*KCG];
__device__ __align__(16) float g_xer  [NEDGE*128];
__device__ __align__(16) float g_xe   [NEDGE*HID];
__device__ __align__(16) float g_xm   [NEDGE*KCG];
__device__ __align__(16) float g_ym   [NEDGE*KCG];
__device__ __align__(16) float g_t3   [3*NEDGE*TPAD];
__device__ __align__(16) float g_mid  [NEDGE*MMID];
__device__ __align__(16) float g_A    [NEDGE*LF];
__device__ __align__(16) float g_feat [2*NEDGE*FEATW];
__device__ __align__(16) float g_h    [2*NEDGE*HID];
__device__ __align__(16) float g_h2   [2*NEDGE*MSGW];
__device__ __align__(16) float g_sh   [NEDGE*LR*CCH];
__device__ __align__(16) float g_msg  [NEDGE*NYR*MSGW];
__device__ __align__(16) float g_m1   [NEDGE*NYR*HID];
__device__ __align__(16) float g_m2   [NEDGE*NYR*MSGW];
__device__ __align__(16) float g_part [4*12288*128];

__device__ __forceinline__ float silu_f(float v) { return v / (1.0f + __expf(-v)); }

// round fp32 -> nearest tf32 value (kept in fp32 container)
__device__ __forceinline__ float rtf(float f) {
    uint32_t r;
    asm("cvt.rna.tf32.f32 %0, %1;" : "=r"(r) : "f"(f));
    return __uint_as_float(r);
}

__device__ __forceinline__ void mma8(float* d, uint32_t a0, uint32_t a1, uint32_t a2,
                                     uint32_t a3, uint32_t b0, uint32_t b1) {
    asm volatile(
        "mma.sync.aligned.m16n8k8.row.col.f32.tf32.tf32.f32 "
        "{%0,%1,%2,%3}, {%4,%5,%6,%7}, {%8,%9}, {%0,%1,%2,%3};"
        : "+f"(d[0]), "+f"(d[1]), "+f"(d[2]), "+f"(d[3])
        : "r"(a0), "r"(a1), "r"(a2), "r"(a3), "r"(b0), "r"(b1));
}

__device__ __forceinline__ void cp16(uint32_t dst, const float* src, bool pred) {
    int sz = pred ? 16 : 0;
    asm volatile("cp.async.cg.shared.global [%0], [%1], 16, %2;"
                 :: "r"(dst), "l"(src), "r"(sz) : "memory");
}
#define CP_COMMIT() asm volatile("cp.async.commit_group;" ::: "memory")
template<int N> __device__ __forceinline__ void cpwait() {
    asm volatile("cp.async.wait_group %0;" :: "n"(N) : "memory");
}

// ---------------------------------------------------------------------------
// tf32 mma.sync GEMM with cp.async pipeline. Inputs MUST be tf32-pre-rounded.
// C[M,N] = A[M,K] @ BT[N,K]^T. CTA 128x128, K-chunks 32, 8 warps, warp 64x32.
// zmode=0: grid.z = split-K (C + z*M*ldc); dual-B keyed on blockIdx.y/ysplit.
// zmode=1: grid.z = batch (A/B by z). EPI: 0 raw, 1 bias+silu, 2 +*xe(row/3).
// ---------------------------------------------------------------------------
#define LDA 36
#define ATILE (128*LDA)
#define BUFSZ (2*ATILE)
#define DYN_SMEM (2*BUFSZ*4)     // 73728 bytes

template<int EPI>
__global__ __launch_bounds__(256, 2)
void tgemm(const float* __restrict__ A0, const float* __restrict__ A1,
           const float* __restrict__ A2,
           const float* __restrict__ B0, const float* __restrict__ B1,
           const float* __restrict__ B2,
           const float* __restrict__ bias0, const float* __restrict__ bias1,
           const float* __restrict__ xe,
           float* __restrict__ C, int M, int Nreal, int K, int ldc,
           int chunksTotal, int chunksPerZ, int zmode, int ysplit)
{
    extern __shared__ uint32_t sm[];
    const uint32_t smBase = (uint32_t)__cvta_generic_to_shared(sm);
    const int tid  = threadIdx.x;
    const int lane = tid & 31;
    const int warp = tid >> 5;
    const int wm = warp >> 2, wn = warp & 3;
    const int g = lane >> 2, t = lane & 3;

    const int bm0 = blockIdx.y * 128;
    const int bn0 = blockIdx.x * 128;
    const int z   = blockIdx.z;

    const float* A;
    const float* BT;
    const float* bias;
    int c0, cend;
    if (zmode) {
        A    = (z == 0) ? A0 : (z == 1) ? A1 : A2;
        BT   = (z == 0) ? B0 : (z == 1) ? B1 : B2;
        bias = bias0;
        c0 = 0; cend = chunksTotal;
    } else {
        A    = A0;
        BT   = ((int)blockIdx.y < ysplit) ? B0 : B1;
        bias = ((int)blockIdx.y < ysplit) ? bias0 : bias1;
        c0 = z * chunksPerZ;
        cend = c0 + chunksPerZ; if (cend > chunksTotal) cend = chunksTotal;
    }

    float acc[4][4][4];
#pragma unroll
    for (int i = 0; i < 4; i++)
#pragma unroll
        for (int j = 0; j < 4; j++)
#pragma unroll
            for (int q = 0; q < 4; q++) acc[i][j][q] = 0.0f;

    const int ldr = tid >> 3;            // 0..31
    const int lseg = tid & 7;

    auto issue = [&](int c, int b) {
        const int kbase = c * 32;
        const int gk = kbase + lseg * 4;
        const bool kok = gk < K;
        uint32_t As = smBase + (uint32_t)(b * BUFSZ) * 4;
        uint32_t Bs = As + ATILE * 4;
#pragma unroll
        for (int i = 0; i < 4; i++) {
            int r = ldr + i * 32;
            cp16(As + (uint32_t)(r * LDA + lseg * 4) * 4,
                 A + (size_t)(bm0 + r) * K + gk, kok);
        }
#pragma unroll
        for (int i = 0; i < 4; i++) {
            int r = ldr + i * 32;
            int gn = bn0 + r;
            cp16(Bs + (uint32_t)(r * LDA + lseg * 4) * 4,
                 BT + (size_t)gn * K + gk, kok && (gn < Nreal));
        }
        CP_COMMIT();
    };

    issue(c0, 0);
    for (int c = c0; c < cend; ++c) {
        int b = (c - c0) & 1;
        if (c + 1 < cend) { issue(c + 1, b ^ 1); cpwait<1>(); }
        else              { cpwait<0>(); }
        __syncthreads();

        const uint32_t* As = sm + b * BUFSZ;
        const uint32_t* Bs = As + ATILE;
#pragma unroll
        for (int kk = 0; kk < 4; kk++) {
            const int k0 = kk * 8;
            uint32_t af[4][4], bf[4][2];
#pragma unroll
            for (int i = 0; i < 4; i++) {
                int mb = wm * 64 + i * 16;
                af[i][0] = As[(mb + g)     * LDA + k0 + t];
                af[i][1] = As[(mb + g + 8) * LDA + k0 + t];
                af[i][2] = As[(mb + g)     * LDA + k0 + t + 4];
                af[i][3] = As[(mb + g + 8) * LDA + k0 + t + 4];
            }
#pragma unroll
            for (int j = 0; j < 4; j++) {
                int nb = wn * 32 + j * 8;
                bf[j][0] = Bs[(nb + g) * LDA + k0 + t];
                bf[j][1] = Bs[(nb + g) * LDA + k0 + t + 4];
            }
#pragma unroll
            for (int i = 0; i < 4; i++)
#pragma unroll
                for (int j = 0; j < 4; j++)
                    mma8(acc[i][j], af[i][0], af[i][1], af[i][2], af[i][3],
                         bf[j][0], bf[j][1]);
        }
        __syncthreads();   // reads of buf b done before it is refilled at c+2
    }

    float* Cz = C + (size_t)z * M * ldc;
#pragma unroll
    for (int i = 0; i < 4; i++) {
        int r0 = bm0 + wm * 64 + i * 16 + g;
#pragma unroll
        for (int j = 0; j < 4; j++) {
            int cc = bn0 + wn * 32 + j * 8 + 2 * t;
#pragma unroll
            for (int half = 0; half < 2; half++) {
                int row = r0 + half * 8;
                float v0 = acc[i][j][half * 2 + 0];
                float v1 = acc[i][j][half * 2 + 1];
                if (cc < Nreal) {
                    if (EPI >= 1) {
                        v0 = silu_f(v0 + bias[cc]);
                        v1 = (cc + 1 < Nreal) ? silu_f(v1 + bias[cc + 1]) : 0.0f;
                    }
                    if (EPI == 2) {
                        const float* xr = xe + (size_t)(row / 3) * 128;
                        v0 *= xr[cc];
                        if (cc + 1 < Nreal) v1 *= xr[cc + 1];
                    }
                    float* cp = Cz + (size_t)row * ldc + cc;
                    if (cc + 1 < Nreal) { float2 fv = make_float2(v0, v1); *(float2*)cp = fv; }
                    else cp[0] = v0;
                }
            }
        }
    }
}

// combine split-K partials: out = epi(sum_z part[z] + bias), tf32-rounded
// (outputs feed the next GEMM). bias1 used for rows >= Mhalf.
template<int EPI>
__global__ void k_combine(const float* __restrict__ part, const float* __restrict__ bias0,
                          const float* __restrict__ bias1, const float* __restrict__ xe,
                          float* __restrict__ outp, int M, int nsplit, int Mhalf)
{
    int idx = blockIdx.x * 256 + threadIdx.x;
    if (idx >= M * 128) return;
    int m = idx >> 7, n = idx & 127;
    float s = (m < Mhalf) ? bias0[n] : bias1[n];
    for (int zz = 0; zz < nsplit; zz++) s += part[(size_t)zz * M * 128 + idx];
    s = silu_f(s);
    if (EPI == 2) s *= xe[(size_t)(m / 3) * 128 + n];
    outp[idx] = rtf(s);
}

// tf32-round a buffer (for external GEMM inputs)
__global__ void k_round(const float* __restrict__ src, float* __restrict__ dst, int n)
{
    int i = blockIdx.x * 256 + threadIdx.x;
    if (i < n) dst[i] = rtf(src[i]);
}

// ---------------- fused multi-transpose (tf32-rounded output) ----------------
struct TD { const float* src; float* dst; int R, C, ldD, tilesX, tileOff; };
struct TDPack { TD d[10]; };

__global__ void k_tmulti(TDPack P, int ndesc)
{
    __shared__ float smt[32][33];
    int bid = blockIdx.x;
    int di = 0;
    for (int i = 1; i < ndesc; i++) if (bid >= P.d[i].tileOff) di = i;
    const TD& D = P.d[di];
    int ti = bid - D.tileOff;
    int c0 = (ti % D.tilesX) * 32;
    int r0 = (ti / D.tilesX) * 32;
    int tx = threadIdx.x & 31, ty = threadIdx.x >> 5;
#pragma unroll
    for (int i = 0; i < 4; i++) {
        int r = r0 + ty + i * 8, c = c0 + tx;
        smt[ty + i * 8][tx] = (r < D.R && c < D.C) ? rtf(D.src[(size_t)r * D.C + c]) : 0.0f;
    }
    __syncthreads();
#pragma unroll
    for (int i = 0; i < 4; i++) {
        int c = c0 + ty + i * 8, r = r0 + tx;
        if (c < D.C && r < D.ldD) D.dst[(size_t)c * D.ldD + r] = smt[tx][ty + i * 8];
    }
}

// ---------------------------------------------------------------------------
// per-edge kernels (R6-proven forms; GEMM-feeding outputs tf32-rounded)
// ---------------------------------------------------------------------------
__global__ void k_xmym(const float* __restrict__ x, const int* __restrict__ eidx,
                       float* __restrict__ xm, float* __restrict__ ym)
{
    int e = blockIdx.x, tid = threadIdx.x;
    int lane = tid & 31, warp = tid >> 5;
    int src = eidx[e], dst = eidx[NEDGE + e];
    const float* ps = x + (size_t)src * XLC;
    const float* pt = x + (size_t)dst * XLC;
    if (tid >= 49 && tid < 64) { xm[e * KCG + tid] = 0.f; ym[e * KCG + tid] = 0.f; }
    for (int l = warp; l < LF; l += 4) {
        const float* a = ps + l * 128;
        const float* b = pt + l * 128;
        float s = a[lane] + a[lane + 32] + a[lane + 64] + a[lane + 96];
        float u = b[lane] + b[lane + 32] + b[lane + 64] + b[lane + 96];
#pragma unroll
        for (int o = 16; o > 0; o >>= 1) {
            s += __shfl_xor_sync(0xffffffffu, s, o);
            u += __shfl_xor_sync(0xffffffffu, u, o);
        }
        if (lane == 0) {
            xm[e * KCG + l] = rtf(s * (1.0f / 128.0f));
            ym[e * KCG + l] = rtf(u * (1.0f / 128.0f));
        }
    }
}

__global__ void k_mid(const float* __restrict__ ym, const float* __restrict__ t,
                      float* __restrict__ mid)
{
    int e = blockIdx.x, tid = threadIdx.x;
    __shared__ float ys[LF];
    if (tid < LF) ys[tid] = ym[e * KCG + tid];
    __syncthreads();
    if (tid < MMID) {
        const float* tp = t + (size_t)e * TPAD + tid;
        float s = 0.0f;
#pragma unroll
        for (int j = 0; j < LF; j++) s = fmaf(ys[j], tp[j * MMID], s);
        mid[e * MMID + tid] = s;
    }
}

__global__ void k_contract2(const float* __restrict__ mid, const float* __restrict__ t1,
                            const float* __restrict__ t2, float* __restrict__ Aout)
{
    int e = blockIdx.x, tid = threadIdx.x;
    __shared__ float ms[MMID];
    if (tid < MMID) ms[tid] = mid[e * MMID + tid];
    __syncthreads();
    if (tid < LF) {
        const float* tp1 = t1 + (size_t)e * TPAD + tid;
        const float* tp2 = t2 + (size_t)e * TPAD + tid;
        float s = 0.0f;
#pragma unroll
        for (int j = 0; j < MMID; j++)
            s = fmaf(ms[j], tp1[j * LF] + tp2[j * LF], s);
        Aout[e * LF + tid] = s;
    }
}

// batched: blocks 0..4095 -> (node=src, other=dst); 4096..8191 -> swapped
__global__ void k_feat(const float* __restrict__ x, const float* __restrict__ glovec,
                       const float* __restrict__ wign, const int* __restrict__ eidx,
                       float* __restrict__ feat)
{
    int e2 = blockIdx.x, tid = threadIdx.x;
    int half = e2 >> 12;
    int e = e2 & 4095;
    __shared__ float wigS[256];
    __shared__ float gS[16];
    __shared__ float red[64];
    int node  = eidx[half ? (NEDGE + e) : e];
    int other = eidx[half ? e : (NEDGE + e)];
    wigS[tid]       = wign[e * 256 + tid];
    wigS[tid + 128] = wign[e * 256 + 128 + tid];
    if (tid < 16) gS[tid] = glovec[other * LR + tid];
    __syncthreads();

    float xr[16];
    const float* xp = x + (size_t)node * XLC;
#pragma unroll
    for (int j = 0; j < 16; j++) xr[j] = xp[j * 128 + tid];

    int lane = tid & 31, warp = tid >> 5;
    float* fp = feat + (size_t)e2 * FEATW;
#pragma unroll
    for (int i = 0; i < 16; i++) {
        float a = 0.0f;
#pragma unroll
        for (int j = 0; j < 16; j++) a = fmaf(wigS[j * 16 + i], xr[j], a);
        fp[i * 129 + tid] = rtf(a);
        float s = a;
#pragma unroll
        for (int o = 16; o > 0; o >>= 1) s += __shfl_xor_sync(0xffffffffu, s, o);
        if (lane == 0) red[i * 4 + warp] = s;
    }
    __syncthreads();
    if (tid < 16) {
        float s = red[tid * 4] + red[tid * 4 + 1] + red[tid * 4 + 2] + red[tid * 4 + 3];
        fp[tid * 129 + 128] = rtf(s * (1.0f / 128.0f) * gS[tid]);
    }
}

// sh[e] = wig_node[e] @ (h2[e] + h2[e+4096])
__global__ void k_sh2(const float* __restrict__ wign, const float* __restrict__ h2,
                      float* __restrict__ sh)
{
    int e = blockIdx.x, tid = threadIdx.x;
    __shared__ float wigS[256];
    wigS[tid]       = wign[e * 256 + tid];
    wigS[tid + 128] = wign[e * 256 + 128 + tid];
    __syncthreads();
    float hr[16];
    const float* hpa = h2 + (size_t)e * MSGW;
    const float* hpb = h2 + (size_t)(e + NEDGE) * MSGW;
#pragma unroll
    for (int j = 0; j < 16; j++) hr[j] = hpa[j * 128 + tid] + hpb[j * 128 + tid];
    float* sp = sh + (size_t)e * MSGW;
#pragma unroll
    for (int i = 0; i < 16; i++) {
        float s = 0.0f;
#pragma unroll
        for (int j = 0; j < 16; j++) s = fmaf(wigS[i * 16 + j], hr[j], s);
        sp[i * 128 + tid] = s;
    }
}

__global__ __launch_bounds__(256)
void k_rotmsg(const float* __restrict__ x, const int* __restrict__ eidx,
              const float* __restrict__ Aarr, const float* __restrict__ sh,
              const float* __restrict__ wigner, float* __restrict__ msg)
{
    int e = blockIdx.x, tid = threadIdx.x;
    __shared__ float zs[LF * 128];
    __shared__ float wgS[48 * 49];
    __shared__ float As_[LF];
    int src = eidx[e], dst = eidx[NEDGE + e];
    const float4* xs4 = (const float4*)(x + (size_t)src * XLC);
    const float4* xt4 = (const float4*)(x + (size_t)dst * XLC);
    const float4* sh4 = (const float4*)(sh + (size_t)e * MSGW);
    if (tid < LF) As_[tid] = Aarr[e * LF + tid];
    __syncthreads();
    float4* zs4 = (float4*)zs;
    for (int i4 = tid; i4 < LF * 32; i4 += 256) {
        int l = i4 >> 5;
        float4 a = xs4[i4], b = xt4[i4];
        float al = As_[l];
        float4 v;
        v.x = 2.0f * (a.x + b.x) + al;
        v.y = 2.0f * (a.y + b.y) + al;
        v.z = 2.0f * (a.z + b.z) + al;
        v.w = 2.0f * (a.w + b.w) + al;
        if (l < 16) {
            float4 s = sh4[i4];
            v.x += s.x; v.y += s.y; v.z += s.z; v.w += s.w;
        }
        zs4[i4] = v;
    }
    const float4* wp4 = (const float4*)(wigner + (size_t)e * (48 * 49));
    float4* wg4 = (float4*)wgS;
    for (int i4 = tid; i4 < 588; i4 += 256) wg4[i4] = wp4[i4];
    __syncthreads();

    int cg = tid & 63, grp = tid >> 6;
    float2 acc[12];
#pragma unroll
    for (int rr = 0; rr < 12; rr++) { acc[rr].x = 0.0f; acc[rr].y = 0.0f; }
    const float2* z2 = (const float2*)zs;
    for (int l = 0; l < LF; l++) {
        float2 zv = z2[l * 64 + cg];
#pragma unroll
        for (int rr = 0; rr < 12; rr++) {
            float w = wgS[(grp * 12 + rr) * LF + l];
            acc[rr].x = fmaf(w, zv.x, acc[rr].x);
            acc[rr].y = fmaf(w, zv.y, acc[rr].y);
        }
    }
    float* mp = msg + (size_t)e * (NYR * MSGW);
#pragma unroll
    for (int rr = 0; rr < 12; rr++) {
        int row = grp * 12 + rr;
        float2 o; o.x = rtf(acc[rr].x); o.y = rtf(acc[rr].y);
        ((float2*)(mp + row * 128))[cg] = o;
    }
}

__global__ __launch_bounds__(256)
void k_out(const float* __restrict__ m2, const float* __restrict__ winv,
           float* __restrict__ out)
{
    int e = blockIdx.x, tid = threadIdx.x;
    __shared__ float mmS[16 * 128];
    __shared__ float wvS[LF * 16];
    const float4* mp4 = (const float4*)(m2 + (size_t)e * (NYR * MSGW));
    float4* mm4 = (float4*)mmS;
    for (int i4 = tid; i4 < 512; i4 += 256) {
        float4 a = mp4[i4], b = mp4[i4 + 512], c = mp4[i4 + 1024];
        float4 v;
        v.x = (a.x + b.x + c.x) * (1.0f / 3.0f);
        v.y = (a.y + b.y + c.y) * (1.0f / 3.0f);
        v.z = (a.z + b.z + c.z) * (1.0f / 3.0f);
        v.w = (a.w + b.w + c.w) * (1.0f / 3.0f);
        mm4[i4] = v;
    }
    const float4* wp4 = (const float4*)(winv + (size_t)e * (LF * 16));
    float4* wv4 = (float4*)wvS;
    for (int i4 = tid; i4 < 196; i4 += 256) wv4[i4] = wp4[i4];
    __syncthreads();

    const float INV3 = 0.5773502691896258f;
    int cg = tid & 63, grp = tid >> 6;
    const float2* mm2 = (const float2*)mmS;
    float* op = out + (size_t)e * XLC;
    for (int b = grp; b < LF; b += 4) {
        float2 s; s.x = 0.0f; s.y = 0.0f;
#pragma unroll
        for (int r = 0; r < 16; r++) {
            float w = wvS[b * 16 + r];
            float2 mv = mm2[r * 64 + cg];
            s.x = fmaf(w, mv.x, s.x);
            s.y = fmaf(w, mv.y, s.y);
        }
        s.x *= INV3; s.y *= INV3;
        ((float2*)(op + b * 128))[cg] = s;
    }
}

// ---------------------------------------------------------------------------
extern "C" void kernel_launch(void* const* d_in, const int* in_sizes, int n_in,
                              void* d_out, int out_size)
{
    const float* x      = (const float*)d_in[0];
    const float* glovec = (const float*)d_in[2];
    const float* x_edge = (const float*)d_in[3];
    const int*   eidx   = (const int*)  d_in[4];
    const float* W_cg1  = (const float*)d_in[8];
    const float* W_cg21 = (const float*)d_in[9];
    const float* W_cg22 = (const float*)d_in[10];
    const float* Wn1a   = (const float*)d_in[11];
    const float* bn1a   = (const float*)d_in[12];
    const float* Wn1b   = (const float*)d_in[13];
    const float* bn1b   = (const float*)d_in[14];
    const float* Wn2a   = (const float*)d_in[15];
    const float* bn2a   = (const float*)d_in[16];
    const float* Wn2b   = (const float*)d_in[17];
    const float* bn2b   = (const float*)d_in[18];
    const float* Wd     = (const float*)d_in[19];
    const float* bd     = (const float*)d_in[20];
    const float* Wp1    = (const float*)d_in[21];
    const float* bp1    = (const float*)d_in[22];
    const float* Wp2    = (const float*)d_in[23];
    const float* bp2    = (const float*)d_in[24];
    const float* wigner = (const float*)d_in[25];
    const float* winv   = (const float*)d_in[26];
    const float* wign   = (const float*)d_in[27];
    float* out = (float*)d_out;

    float *pWdT, *pW1aT, *pW1bT, *pW2aT, *pW2bT, *pWp1T, *pWp2T, *pWc1T, *pWc2T, *pWc3T;
    float *p_xer, *p_xe, *p_xm, *p_ym, *p_t3, *p_mid, *p_A, *p_feat, *p_h, *p_h2,
          *p_sh, *p_msg, *p_m1, *p_m2, *p_part;
    cudaGetSymbolAddress((void**)&pWdT,  g_WdT);
    cudaGetSymbolAddress((void**)&pW1aT, g_Wn1aT);
    cudaGetSymbolAddress((void**)&pW1bT, g_Wn1bT);
    cudaGetSymbolAddress((void**)&pW2aT, g_Wn2aT);
    cudaGetSymbolAddress((void**)&pW2bT, g_Wn2bT);
    cudaGetSymbolAddress((void**)&pWp1T, g_Wp1T);
    cudaGetSymbolAddress((void**)&pWp2T, g_Wp2T);
    cudaGetSymbolAddress((void**)&pWc1T, g_Wc1T);
    cudaGetSymbolAddress((void**)&pWc2T, g_Wc2T);
    cudaGetSymbolAddress((void**)&pWc3T, g_Wc3T);
    cudaGetSymbolAddress((void**)&p_xer,  g_xer);
    cudaGetSymbolAddress((void**)&p_xe,   g_xe);
    cudaGetSymbolAddress((void**)&p_xm,   g_xm);
    cudaGetSymbolAddress((void**)&p_ym,   g_ym);
    cudaGetSymbolAddress((void**)&p_t3,   g_t3);
    cudaGetSymbolAddress((void**)&p_mid,  g_mid);
    cudaGetSymbolAddress((void**)&p_A,    g_A);
    cudaGetSymbolAddress((void**)&p_feat, g_feat);
    cudaGetSymbolAddress((void**)&p_h,    g_h);
    cudaGetSymbolAddress((void**)&p_h2,   g_h2);
    cudaGetSymbolAddress((void**)&p_sh,   g_sh);
    cudaGetSymbolAddress((void**)&p_msg,  g_msg);
    cudaGetSymbolAddress((void**)&p_m1,   g_m1);
    cudaGetSymbolAddress((void**)&p_m2,   g_m2);
    cudaGetSymbolAddress((void**)&p_part, g_part);

    cudaFuncSetAttribute(tgemm<0>, cudaFuncAttributeMaxDynamicSharedMemorySize, DYN_SMEM);
    cudaFuncSetAttribute(tgemm<1>, cudaFuncAttributeMaxDynamicSharedMemorySize, DYN_SMEM);
    cudaFuncSetAttribute(tgemm<2>, cudaFuncAttributeMaxDynamicSharedMemorySize, DYN_SMEM);

    const int BIG = 1 << 30;

    // ---- weight transposes (tf32-rounded) in ONE launch + x_edge rounding ----
    {
        TDPack P;
        auto set = [&](int i, const float* s, float* dst, int R, int C, int ldD, int& off) {
            int tx = (C + 31) / 32, ty = (ldD + 31) / 32;
            P.d[i] = TD{ s, dst, R, C, ldD, tx, off };
            off += tx * ty;
        };
        int off = 0;
        set(0, Wd,    pWdT,  128,  128,  128,  off);
        set(1, Wn1a,  pW1aT, FEATW,128,  FEATW,off);
        set(2, Wn1b,  pW1bT, 128,  2048, 128,  off);
        set(3, Wn2a,  pW2aT, FEATW,128,  FEATW,off);
        set(4, Wn2b,  pW2bT, 128,  2048, 128,  off);
        set(5, Wp1,   pWp1T, 2048, 128,  2048, off);
        set(6, Wp2,   pWp2T, 128,  2048, 128,  off);
        set(7, W_cg1, pWc1T, 49,   1225, KCG,  off);
        set(8, W_cg21,pWc2T, 49,   1225, KCG,  off);
        set(9, W_cg22,pWc3T, 49,   1225, KCG,  off);
        k_tmulti<<<off, 256>>>(P, 10);
    }
    k_round<<<(NEDGE * 128 + 255) / 256, 256>>>(x_edge, p_xer, NEDGE * 128);

    // 1. xe = silu(x_edge @ Wd + bd)
    tgemm<1><<<dim3(1, 32, 1), 256, DYN_SMEM>>>(
        p_xer, nullptr, nullptr, pWdT, nullptr, nullptr, bd, nullptr, nullptr,
        p_xe, NEDGE, 128, 128, 128, 4, 4, 0, BIG);

    // 2. channel means (K padded to 64)
    k_xmym<<<NEDGE, 128>>>(x, eidx, p_xm, p_ym);

    // 3. CG bilinears: batched z=3
    tgemm<0><<<dim3(10, 32, 3), 256, DYN_SMEM>>>(
        p_xm, p_xm, p_ym, pWc1T, pWc2T, pWc3T, nullptr, nullptr, nullptr,
        p_t3, NEDGE, 1225, KCG, TPAD, 2, 2, 1, BIG);
    k_mid<<<NEDGE, 64>>>(p_ym, p_t3, p_mid);
    k_contract2<<<NEDGE, 64>>>(p_mid, p_t3 + (size_t)NEDGE * TPAD,
                               p_t3 + 2 * (size_t)NEDGE * TPAD, p_A);

    // 4+5. node_interactions batched
    k_feat<<<2 * NEDGE, 128>>>(x, glovec, wign, eidx, p_feat);
    tgemm<0><<<dim3(1, 64, 4), 256, DYN_SMEM>>>(
        p_feat, nullptr, nullptr, pW1aT, pW2aT, nullptr, nullptr, nullptr, nullptr,
        p_part, 2 * NEDGE, 128, FEATW, 128, 65, 17, 0, 32);
    k_combine<1><<<(2 * NEDGE * 128 + 255) / 256, 256>>>(
        p_part, bn1a, bn2a, nullptr, p_h, 2 * NEDGE, 4, NEDGE);
    tgemm<1><<<dim3(16, 64, 1), 256, DYN_SMEM>>>(
        p_h, nullptr, nullptr, pW1bT, pW2bT, nullptr, bn1b, bn2b, nullptr,
        p_h2, 2 * NEDGE, 2048, 128, 2048, 4, 4, 0, 32);
    k_sh2<<<NEDGE, 128>>>(wign, p_h2, p_sh);

    // 6. fused z-build + rotate (msg tf32-rounded for Wp1 GEMM)
    k_rotmsg<<<NEDGE, 256>>>(x, eidx, p_A, p_sh, wigner, p_msg);

    // 7. edge MLP
    tgemm<0><<<dim3(1, 96, 2), 256, DYN_SMEM>>>(
        p_msg, nullptr, nullptr, pWp1T, nullptr, nullptr, nullptr, nullptr, nullptr,
        p_part, NEDGE * NYR, 128, 2048, 128, 64, 32, 0, BIG);
    k_combine<2><<<(NEDGE * NYR * 128 + 255) / 256, 256>>>(
        p_part, bp1, bp1, p_xe, p_m1, NEDGE * NYR, 2, BIG);
    tgemm<1><<<dim3(16, 96, 1), 256, DYN_SMEM>>>(
        p_m1, nullptr, nullptr, pWp2T, nullptr, nullptr, bp2, nullptr, nullptr,
        p_m2, NEDGE * NYR, 2048, 128, 2048, 4, 4, 0, BIG);

    // 8. NY-mean + inverse rotation
    k_out<<<NEDGE, 256>>>(p_m2, winv, out);
}

// round 9
// speedup vs baseline: 1.2474x; 1.2474x over previous
#include <cuda_runtime.h>
#include <cstdint>
#include <math.h>

// ---------------- problem constants ----------------
#define NNODE 2048
#define NEDGE 4096
#define LF    49
#define LR    16
#define MMID  25
#define NYR   3
#define CCH   128
#define HID   128
#define XLC   (LF*CCH)      // 6272
#define FEATW 2064          // 16*129
#define MSGW  2048          // 16*128
#define TPAD  1280          // padded 1225
#define KCG   64            // padded 49

// ---------------- device scratch ----------------
__device__ __align__(16) float g_WdT  [128*128];
__device__ __align__(16) float g_Wn1aT[128*FEATW];
__device__ __align__(16) float g_Wn1bT[2048*128];
__device__ __align__(16) float g_Wn2aT[128*FEATW];
__device__ __align__(16) float g_Wn2bT[2048*128];
__device__ __align__(16) float g_Wp1T [128*2048];
__device__ __align__(16) float g_Wp2T [2048*128];
__device__ __align__(16) float g_Wc1T [TPAD*KCG];
__device__ __align__(16) float g_Wc2T [TPAD*KCG];
__device__ __align__(16) float g_Wc3T [TPAD*KCG];
__device__ __align__(16) float g_xe   [NEDGE*HID];
__device__ __align__(16) float g_xm   [NEDGE*KCG];
__device__ __align__(16) float g_ym   [NEDGE*KCG];
__device__ __align__(16) float g_t3   [3*NEDGE*TPAD];
__device__ __align__(16) float g_A    [NEDGE*LF];
__device__ __align__(16) float g_feat [2*NEDGE*FEATW];
__device__ __align__(16) float g_h    [2*NEDGE*HID];
__device__ __align__(16) float g_h2   [2*NEDGE*MSGW];
__device__ __align__(16) float g_sh   [NEDGE*LR*CCH];
__device__ __align__(16) float g_msg  [NEDGE*NYR*MSGW];
__device__ __align__(16) float g_m1   [NEDGE*NYR*HID];
__device__ __align__(16) float g_m2   [NEDGE*NYR*MSGW];
__device__ __align__(16) float g_part [4*12288*128];

__device__ __forceinline__ float silu_f(float v) { return v / (1.0f + __expf(-v)); }

__device__ __forceinline__ uint32_t f2tf32(float f) {
    uint32_t r;
    asm("cvt.rna.tf32.f32 %0, %1;" : "=r"(r) : "f"(f));
    return r;
}

__device__ __forceinline__ void mma8(float* d, uint32_t a0, uint32_t a1, uint32_t a2,
                                     uint32_t a3, uint32_t b0, uint32_t b1) {
    asm volatile(
        "mma.sync.aligned.m16n8k8.row.col.f32.tf32.tf32.f32 "
        "{%0,%1,%2,%3}, {%4,%5,%6,%7}, {%8,%9}, {%0,%1,%2,%3};"
        : "+f"(d[0]), "+f"(d[1]), "+f"(d[2]), "+f"(d[3])
        : "r"(a0), "r"(a1), "r"(a2), "r"(a3), "r"(b0), "r"(b1));
}

// ---------------------------------------------------------------------------
// tf32 mma.sync GEMM (R6-proven): C[M,N] = A[M,K] @ BT[N,K]^T.
// CTA 128x128, K chunks 32, 8 warps (2x4), warp tile 64x32, occ 1.
// zmode=0: grid.z = split-K (C + z*M*ldc); dual-B keyed on blockIdx.y/ysplit.
// zmode=1: grid.z = batch (A/B by z).
// EPI: 0=raw, 1=bias+silu, 2=bias+silu then *= xe[(row/3)*128+col]
// ---------------------------------------------------------------------------
#define LDA 36
#define ATILE (128*LDA)
#define BUFSZ (2*ATILE)
#define DYN_SMEM (2*BUFSZ*4)     // 73728 bytes

template<int EPI>
__global__ __launch_bounds__(256, 1)
void tgemm(const float* __restrict__ A0, const float* __restrict__ A1,
           const float* __restrict__ A2,
           const float* __restrict__ B0, const float* __restrict__ B1,
           const float* __restrict__ B2,
           const float* __restrict__ bias0, const float* __restrict__ bias1,
           const float* __restrict__ xe,
           float* __restrict__ C, int M, int Nreal, int K, int ldc,
           int chunksTotal, int chunksPerZ, int zmode, int ysplit)
{
    extern __shared__ uint32_t sm[];
    const int tid  = threadIdx.x;
    const int lane = tid & 31;
    const int warp = tid >> 5;
    const int wm = warp >> 2, wn = warp & 3;
    const int g = lane >> 2, t = lane & 3;

    const int bm0 = blockIdx.y * 128;
    const int bn0 = blockIdx.x * 128;
    const int z   = blockIdx.z;

    const float* A;
    const float* BT;
    const float* bias;
    int c0, cend;
    if (zmode) {
        A    = (z == 0) ? A0 : (z == 1) ? A1 : A2;
        BT   = (z == 0) ? B0 : (z == 1) ? B1 : B2;
        bias = bias0;
        c0 = 0; cend = chunksTotal;
    } else {
        A    = A0;
        BT   = ((int)blockIdx.y < ysplit) ? B0 : B1;
        bias = ((int)blockIdx.y < ysplit) ? bias0 : bias1;
        c0 = z * chunksPerZ;
        cend = c0 + chunksPerZ; if (cend > chunksTotal) cend = chunksTotal;
    }

    float acc[4][4][4];
#pragma unroll
    for (int i = 0; i < 4; i++)
#pragma unroll
        for (int j = 0; j < 4; j++)
#pragma unroll
            for (int q = 0; q < 4; q++) acc[i][j][q] = 0.0f;

    const int ldr = tid >> 3;            // 0..31
    const int lseg = tid & 7;
    float4 pa[4], pb[4];

    auto loadRegs = [&](int c) {
        const int kbase = c * 32;
#pragma unroll
        for (int i = 0; i < 4; i++) {
            int r = ldr + i * 32;
            int gk = kbase + lseg * 4;
            float4 v = make_float4(0.f, 0.f, 0.f, 0.f);
            if (gk < K) v = *(const float4*)(A + (size_t)(bm0 + r) * K + gk);
            pa[i] = v;
        }
#pragma unroll
        for (int i = 0; i < 4; i++) {
            int r = ldr + i * 32;
            int gn = bn0 + r, gk = kbase + lseg * 4;
            float4 v = make_float4(0.f, 0.f, 0.f, 0.f);
            if (gn < Nreal && gk < K) v = *(const float4*)(BT + (size_t)gn * K + gk);
            pb[i] = v;
        }
    };

    auto storeRegs = [&](int b) {
        uint32_t* As = sm + b * BUFSZ;
        uint32_t* Bs = As + ATILE;
#pragma unroll
        for (int i = 0; i < 4; i++) {
            int r = ldr + i * 32;
            uint32_t* p = As + r * LDA + lseg * 4;
            p[0] = f2tf32(pa[i].x); p[1] = f2tf32(pa[i].y);
            p[2] = f2tf32(pa[i].z); p[3] = f2tf32(pa[i].w);
        }
#pragma unroll
        for (int i = 0; i < 4; i++) {
            int r = ldr + i * 32;
            uint32_t* p = Bs + r * LDA + lseg * 4;
            p[0] = f2tf32(pb[i].x); p[1] = f2tf32(pb[i].y);
            p[2] = f2tf32(pb[i].z); p[3] = f2tf32(pb[i].w);
        }
    };

    loadRegs(c0);
    for (int c = c0; c < cend; ++c) {
        int b = (c - c0) & 1;
        storeRegs(b);
        __syncthreads();
        if (c + 1 < cend) loadRegs(c + 1);

        const uint32_t* As = sm + b * BUFSZ;
        const uint32_t* Bs = As + ATILE;
#pragma unroll
        for (int kk = 0; kk < 4; kk++) {
            const int k0 = kk * 8;
            uint32_t af[4][4], bf[4][2];
#pragma unroll
            for (int i = 0; i < 4; i++) {
                int mb = wm * 64 + i * 16;
                af[i][0] = As[(mb + g)     * LDA + k0 + t];
                af[i][1] = As[(mb + g + 8) * LDA + k0 + t];
                af[i][2] = As[(mb + g)     * LDA + k0 + t + 4];
                af[i][3] = As[(mb + g + 8) * LDA + k0 + t + 4];
            }
#pragma unroll
            for (int j = 0; j < 4; j++) {
                int nb = wn * 32 + j * 8;
                bf[j][0] = Bs[(nb + g) * LDA + k0 + t];
                bf[j][1] = Bs[(nb + g) * LDA + k0 + t + 4];
            }
#pragma unroll
            for (int i = 0; i < 4; i++)
#pragma unroll
                for (int j = 0; j < 4; j++)
                    mma8(acc[i][j], af[i][0], af[i][1], af[i][2], af[i][3],
                         bf[j][0], bf[j][1]);
        }
        // single barrier per chunk: buffer b only re-stored after every warp
        // has passed the NEXT iteration's barrier (post its mma on b). Safe.
    }

    float* Cz = C + (size_t)z * M * ldc;
#pragma unroll
    for (int i = 0; i < 4; i++) {
        int r0 = bm0 + wm * 64 + i * 16 + g;
#pragma unroll
        for (int j = 0; j < 4; j++) {
            int cc = bn0 + wn * 32 + j * 8 + 2 * t;
#pragma unroll
            for (int half = 0; half < 2; half++) {
                int row = r0 + half * 8;
                float v0 = acc[i][j][half * 2 + 0];
                float v1 = acc[i][j][half * 2 + 1];
                if (cc < Nreal) {
                    if (EPI >= 1) {
                        v0 = silu_f(v0 + bias[cc]);
                        v1 = (cc + 1 < Nreal) ? silu_f(v1 + bias[cc + 1]) : 0.0f;
                    }
                    if (EPI == 2) {
                        const float* xr = xe + (size_t)(row / 3) * 128;
                        v0 *= xr[cc];
                        if (cc + 1 < Nreal) v1 *= xr[cc + 1];
                    }
                    float* cp = Cz + (size_t)row * ldc + cc;
                    if (cc + 1 < Nreal) { float2 fv = make_float2(v0, v1); *(float2*)cp = fv; }
                    else cp[0] = v0;
                }
            }
        }
    }
}

// combine split-K partials: out = epi(sum_z part[z] + bias); bias1 for rows>=Mhalf
template<int EPI>
__global__ void k_combine(const float* __restrict__ part, const float* __restrict__ bias0,
                          const float* __restrict__ bias1, const float* __restrict__ xe,
                          float* __restrict__ outp, int M, int nsplit, int Mhalf)
{
    int idx = blockIdx.x * 256 + threadIdx.x;
    if (idx >= M * 128) return;
    int m = idx >> 7, n = idx & 127;
    float s = (m < Mhalf) ? bias0[n] : bias1[n];
    for (int zz = 0; zz < nsplit; zz++) s += part[(size_t)zz * M * 128 + idx];
    s = silu_f(s);
    if (EPI == 2) s *= xe[(size_t)(m / 3) * 128 + n];
    outp[idx] = s;
}

// ---------------- fused multi-transpose ----------------
struct TD { const float* src; float* dst; int R, C, ldD, tilesX, tileOff; };
struct TDPack { TD d[10]; };

__global__ void k_tmulti(TDPack P, int ndesc)
{
    __shared__ float smt[32][33];
    int bid = blockIdx.x;
    int di = 0;
    for (int i = 1; i < ndesc; i++) if (bid >= P.d[i].tileOff) di = i;
    const TD& D = P.d[di];
    int ti = bid - D.tileOff;
    int c0 = (ti % D.tilesX) * 32;
    int r0 = (ti / D.tilesX) * 32;
    int tx = threadIdx.x & 31, ty = threadIdx.x >> 5;
#pragma unroll
    for (int i = 0; i < 4; i++) {
        int r = r0 + ty + i * 8, c = c0 + tx;
        smt[ty + i * 8][tx] = (r < D.R && c < D.C) ? D.src[(size_t)r * D.C + c] : 0.0f;
    }
    __syncthreads();
#pragma unroll
    for (int i = 0; i < 4; i++) {
        int c = c0 + ty + i * 8, r = r0 + tx;
        if (c < D.C && r < D.ldD) D.dst[(size_t)c * D.ldD + r] = smt[tx][ty + i * 8];
    }
}

// ---------------------------------------------------------------------------
// per-edge kernels
// ---------------------------------------------------------------------------
// float4-vectorized: warp w handles rows l = w, w+4, ...; lane reads float4.
__global__ void k_xmym(const float* __restrict__ x, const int* __restrict__ eidx,
                       float* __restrict__ xm, float* __restrict__ ym)
{
    int e = blockIdx.x, tid = threadIdx.x;
    int lane = tid & 31, warp = tid >> 5;
    int src = eidx[e], dst = eidx[NEDGE + e];
    const float4* ps = (const float4*)(x + (size_t)src * XLC);
    const float4* pt = (const float4*)(x + (size_t)dst * XLC);
    if (tid >= 49 && tid < 64) { xm[e * KCG + tid] = 0.f; ym[e * KCG + tid] = 0.f; }
    for (int l = warp; l < LF; l += 4) {
        float4 a = ps[l * 32 + lane];
        float4 b = pt[l * 32 + lane];
        float s = (a.x + a.y) + (a.z + a.w);
        float u = (b.x + b.y) + (b.z + b.w);
#pragma unroll
        for (int o = 16; o > 0; o >>= 1) {
            s += __shfl_xor_sync(0xffffffffu, s, o);
            u += __shfl_xor_sync(0xffffffffu, u, o);
        }
        if (lane == 0) {
            xm[e * KCG + l] = s * (1.0f / 128.0f);
            ym[e * KCG + l] = u * (1.0f / 128.0f);
        }
    }
}

// merged: mid[o] = sum_j ym[j] * t1[j*25+o]; then A[o] = sum_j mid[j]*(t2+t3)[j*49+o]
__global__ void k_midcon(const float* __restrict__ ym, const float* __restrict__ t1,
                         const float* __restrict__ t2, const float* __restrict__ t3,
                         float* __restrict__ Aout)
{
    int e = blockIdx.x, tid = threadIdx.x;   // 64 threads
    __shared__ float ys[LF];
    __shared__ float ms[MMID];
    if (tid < LF) ys[tid] = ym[e * KCG + tid];
    __syncthreads();
    if (tid < MMID) {
        const float* tp = t1 + (size_t)e * TPAD + tid;
        float s = 0.0f;
#pragma unroll
        for (int j = 0; j < LF; j++) s = fmaf(ys[j], tp[j * MMID], s);
        ms[tid] = s;
    }
    __syncthreads();
    if (tid < LF) {
        const float* tp2 = t2 + (size_t)e * TPAD + tid;
        const float* tp3 = t3 + (size_t)e * TPAD + tid;
        float s = 0.0f;
#pragma unroll
        for (int j = 0; j < MMID; j++)
            s = fmaf(ms[j], tp2[j * LF] + tp3[j * LF], s);
        Aout[e * LF + tid] = s;
    }
}

// batched: blocks 0..4095 -> (node=src, other=dst); 4096..8191 -> swapped
__global__ void k_feat(const float* __restrict__ x, const float* __restrict__ glovec,
                       const float* __restrict__ wign, const int* __restrict__ eidx,
                       float* __restrict__ feat)
{
    int e2 = blockIdx.x, tid = threadIdx.x;
    int half = e2 >> 12;
    int e = e2 & 4095;
    __shared__ float wigS[256];
    __shared__ float gS[16];
    __shared__ float red[64];
    int node  = eidx[half ? (NEDGE + e) : e];
    int other = eidx[half ? e : (NEDGE + e)];
    wigS[tid]       = wign[e * 256 + tid];
    wigS[tid + 128] = wign[e * 256 + 128 + tid];
    if (tid < 16) gS[tid] = glovec[other * LR + tid];
    __syncthreads();

    float xr[16];
    const float* xp = x + (size_t)node * XLC;
#pragma unroll
    for (int j = 0; j < 16; j++) xr[j] = xp[j * 128 + tid];

    int lane = tid & 31, warp = tid >> 5;
    float* fp = feat + (size_t)e2 * FEATW;
#pragma unroll
    for (int i = 0; i < 16; i++) {
        float a = 0.0f;
#pragma unroll
        for (int j = 0; j < 16; j++) a = fmaf(wigS[j * 16 + i], xr[j], a);
        fp[i * 129 + tid] = a;
        float s = a;
#pragma unroll
        for (int o = 16; o > 0; o >>= 1) s += __shfl_xor_sync(0xffffffffu, s, o);
        if (lane == 0) red[i * 4 + warp] = s;
    }
    __syncthreads();
    if (tid < 16) {
        float s = red[tid * 4] + red[tid * 4 + 1] + red[tid * 4 + 2] + red[tid * 4 + 3];
        fp[tid * 129 + 128] = s * (1.0f / 128.0f) * gS[tid];
    }
}

// sh[e] = wig_node[e] @ (h2[e] + h2[e+4096])
__global__ void k_sh2(const float* __restrict__ wign, const float* __restrict__ h2,
                      float* __restrict__ sh)
{
    int e = blockIdx.x, tid = threadIdx.x;
    __shared__ float wigS[256];
    wigS[tid]       = wign[e * 256 + tid];
    wigS[tid + 128] = wign[e * 256 + 128 + tid];
    __syncthreads();
    float hr[16];
    const float* hpa = h2 + (size_t)e * MSGW;
    const float* hpb = h2 + (size_t)(e + NEDGE) * MSGW;
#pragma unroll
    for (int j = 0; j < 16; j++) hr[j] = hpa[j * 128 + tid] + hpb[j * 128 + tid];
    float* sp = sh + (size_t)e * MSGW;
#pragma unroll
    for (int i = 0; i < 16; i++) {
        float s = 0.0f;
#pragma unroll
        for (int j = 0; j < 16; j++) s = fmaf(wigS[i * 16 + j], hr[j], s);
        sp[i * 128 + tid] = s;
    }
}

__global__ __launch_bounds__(256)
void k_rotmsg(const float* __restrict__ x, const int* __restrict__ eidx,
              const float* __restrict__ Aarr, const float* __restrict__ sh,
              const float* __restrict__ wigner, float* __restrict__ msg)
{
    int e = blockIdx.x, tid = threadIdx.x;
    __shared__ float zs[LF * 128];
    __shared__ float wgS[48 * 49];
    __shared__ float As_[LF];
    int src = eidx[e], dst = eidx[NEDGE + e];
    const float4* xs4 = (const float4*)(x + (size_t)src * XLC);
    const float4* xt4 = (const float4*)(x + (size_t)dst * XLC);
    const float4* sh4 = (const float4*)(sh + (size_t)e * MSGW);
    if (tid < LF) As_[tid] = Aarr[e * LF + tid];
    __syncthreads();
    float4* zs4 = (float4*)zs;
    for (int i4 = tid; i4 < LF * 32; i4 += 256) {
        int l = i4 >> 5;
        float4 a = xs4[i4], b = xt4[i4];
        float al = As_[l];
        float4 v;
        v.x = 2.0f * (a.x + b.x) + al;
        v.y = 2.0f * (a.y + b.y) + al;
        v.z = 2.0f * (a.z + b.z) + al;
        v.w = 2.0f * (a.w + b.w) + al;
        if (l < 16) {
            float4 s = sh4[i4];
            v.x += s.x; v.y += s.y; v.z += s.z; v.w += s.w;
        }
        zs4[i4] = v;
    }
    const float4* wp4 = (const float4*)(wigner + (size_t)e * (48 * 49));
    float4* wg4 = (float4*)wgS;
    for (int i4 = tid; i4 < 588; i4 += 256) wg4[i4] = wp4[i4];
    __syncthreads();

    int cg = tid & 63, grp = tid >> 6;
    float2 acc[12];
#pragma unroll
    for (int rr = 0; rr < 12; rr++) { acc[rr].x = 0.0f; acc[rr].y = 0.0f; }
    const float2* z2 = (const float2*)zs;
    for (int l = 0; l < LF; l++) {
        float2 zv = z2[l * 64 + cg];
#pragma unroll
        for (int rr = 0; rr < 12; rr++) {
            float w = wgS[(grp * 12 + rr) * LF + l];
            acc[rr].x = fmaf(w, zv.x, acc[rr].x);
            acc[rr].y = fmaf(w, zv.y, acc[rr].y);
        }
    }
    float* mp = msg + (size_t)e * (NYR * MSGW);
#pragma unroll
    for (int rr = 0; rr < 12; rr++) {
        int row = grp * 12 + rr;
        ((float2*)(mp + row * 128))[cg] = acc[rr];
    }
}

__global__ __launch_bounds__(256)
void k_out(const float* __restrict__ m2, const float* __restrict__ winv,
           float* __restrict__ out)
{
    int e = blockIdx.x, tid = threadIdx.x;
    __shared__ float mmS[16 * 128];
    __shared__ float wvS[LF * 16];
    const float4* mp4 = (const float4*)(m2 + (size_t)e * (NYR * MSGW));
    float4* mm4 = (float4*)mmS;
    for (int i4 = tid; i4 < 512; i4 += 256) {
        float4 a = mp4[i4], b = mp4[i4 + 512], c = mp4[i4 + 1024];
        float4 v;
        v.x = (a.x + b.x + c.x) * (1.0f / 3.0f);
        v.y = (a.y + b.y + c.y) * (1.0f / 3.0f);
        v.z = (a.z + b.z + c.z) * (1.0f / 3.0f);
        v.w = (a.w + b.w + c.w) * (1.0f / 3.0f);
        mm4[i4] = v;
    }
    const float4* wp4 = (const float4*)(winv + (size_t)e * (LF * 16));
    float4* wv4 = (float4*)wvS;
    for (int i4 = tid; i4 < 196; i4 += 256) wv4[i4] = wp4[i4];
    __syncthreads();

    const float INV3 = 0.5773502691896258f;
    int cg = tid & 63, grp = tid >> 6;
    const float2* mm2 = (const float2*)mmS;
    float* op = out + (size_t)e * XLC;
    for (int b = grp; b < LF; b += 4) {
        float2 s; s.x = 0.0f; s.y = 0.0f;
#pragma unroll
        for (int r = 0; r < 16; r++) {
            float w = wvS[b * 16 + r];
            float2 mv = mm2[r * 64 + cg];
            s.x = fmaf(w, mv.x, s.x);
            s.y = fmaf(w, mv.y, s.y);
        }
        s.x *= INV3; s.y *= INV3;
        ((float2*)(op + b * 128))[cg] = s;
    }
}

// ---------------------------------------------------------------------------
extern "C" void kernel_launch(void* const* d_in, const int* in_sizes, int n_in,
                              void* d_out, int out_size)
{
    const float* x      = (const float*)d_in[0];
    const float* glovec = (const float*)d_in[2];
    const float* x_edge = (const float*)d_in[3];
    const int*   eidx   = (const int*)  d_in[4];
    const float* W_cg1  = (const float*)d_in[8];
    const float* W_cg21 = (const float*)d_in[9];
    const float* W_cg22 = (const float*)d_in[10];
    const float* Wn1a   = (const float*)d_in[11];
    const float* bn1a   = (const float*)d_in[12];
    const float* Wn1b   = (const float*)d_in[13];
    const float* bn1b   = (const float*)d_in[14];
    const float* Wn2a   = (const float*)d_in[15];
    const float* bn2a   = (const float*)d_in[16];
    const float* Wn2b   = (const float*)d_in[17];
    const float* bn2b   = (const float*)d_in[18];
    const float* Wd     = (const float*)d_in[19];
    const float* bd     = (const float*)d_in[20];
    const float* Wp1    = (const float*)d_in[21];
    const float* bp1    = (const float*)d_in[22];
    const float* Wp2    = (const float*)d_in[23];
    const float* bp2    = (const float*)d_in[24];
    const float* wigner = (const float*)d_in[25];
    const float* winv   = (const float*)d_in[26];
    const float* wign   = (const float*)d_in[27];
    float* out = (float*)d_out;

    float *pWdT, *pW1aT, *pW1bT, *pW2aT, *pW2bT, *pWp1T, *pWp2T, *pWc1T, *pWc2T, *pWc3T;
    float *p_xe, *p_xm, *p_ym, *p_t3, *p_A, *p_feat, *p_h, *p_h2,
          *p_sh, *p_msg, *p_m1, *p_m2, *p_part;
    cudaGetSymbolAddress((void**)&pWdT,  g_WdT);
    cudaGetSymbolAddress((void**)&pW1aT, g_Wn1aT);
    cudaGetSymbolAddress((void**)&pW1bT, g_Wn1bT);
    cudaGetSymbolAddress((void**)&pW2aT, g_Wn2aT);
    cudaGetSymbolAddress((void**)&pW2bT, g_Wn2bT);
    cudaGetSymbolAddress((void**)&pWp1T, g_Wp1T);
    cudaGetSymbolAddress((void**)&pWp2T, g_Wp2T);
    cudaGetSymbolAddress((void**)&pWc1T, g_Wc1T);
    cudaGetSymbolAddress((void**)&pWc2T, g_Wc2T);
    cudaGetSymbolAddress((void**)&pWc3T, g_Wc3T);
    cudaGetSymbolAddress((void**)&p_xe,   g_xe);
    cudaGetSymbolAddress((void**)&p_xm,   g_xm);
    cudaGetSymbolAddress((void**)&p_ym,   g_ym);
    cudaGetSymbolAddress((void**)&p_t3,   g_t3);
    cudaGetSymbolAddress((void**)&p_A,    g_A);
    cudaGetSymbolAddress((void**)&p_feat, g_feat);
    cudaGetSymbolAddress((void**)&p_h,    g_h);
    cudaGetSymbolAddress((void**)&p_h2,   g_h2);
    cudaGetSymbolAddress((void**)&p_sh,   g_sh);
    cudaGetSymbolAddress((void**)&p_msg,  g_msg);
    cudaGetSymbolAddress((void**)&p_m1,   g_m1);
    cudaGetSymbolAddress((void**)&p_m2,   g_m2);
    cudaGetSymbolAddress((void**)&p_part, g_part);

    cudaFuncSetAttribute(tgemm<0>, cudaFuncAttributeMaxDynamicSharedMemorySize, DYN_SMEM);
    cudaFuncSetAttribute(tgemm<1>, cudaFuncAttributeMaxDynamicSharedMemorySize, DYN_SMEM);
    cudaFuncSetAttribute(tgemm<2>, cudaFuncAttributeMaxDynamicSharedMemorySize, DYN_SMEM);

    const int BIG = 1 << 30;

    // ---- all weight transposes in ONE launch ----
    {
        TDPack P;
        auto set = [&](int i, const float* s, float* dst, int R, int C, int ldD, int& off) {
            int tx = (C + 31) / 32, ty = (ldD + 31) / 32;
            P.d[i] = TD{ s, dst, R, C, ldD, tx, off };
            off += tx * ty;
        };
        int off = 0;
        set(0, Wd,    pWdT,  128,  128,  128,  off);
        set(1, Wn1a,  pW1aT, FEATW,128,  FEATW,off);
        set(2, Wn1b,  pW1bT, 128,  2048, 128,  off);
        set(3, Wn2a,  pW2aT, FEATW,128,  FEATW,off);
        set(4, Wn2b,  pW2bT, 128,  2048, 128,  off);
        set(5, Wp1,   pWp1T, 2048, 128,  2048, off);
        set(6, Wp2,   pWp2T, 128,  2048, 128,  off);
        set(7, W_cg1, pWc1T, 49,   1225, KCG,  off);
        set(8, W_cg21,pWc2T, 49,   1225, KCG,  off);
        set(9, W_cg22,pWc3T, 49,   1225, KCG,  off);
        k_tmulti<<<off, 256>>>(P, 10);
    }

    // 1. xe = silu(x_edge @ Wd + bd)
    tgemm<1><<<dim3(1, 32, 1), 256, DYN_SMEM>>>(
        x_edge, nullptr, nullptr, pWdT, nullptr, nullptr, bd, nullptr, nullptr,
        p_xe, NEDGE, 128, 128, 128, 4, 4, 0, BIG);

    // 2. channel means (K padded to 64)
    k_xmym<<<NEDGE, 128>>>(x, eidx, p_xm, p_ym);

    // 3. CG bilinears: batched z=3, then fused mid+contract
    tgemm<0><<<dim3(10, 32, 3), 256, DYN_SMEM>>>(
        p_xm, p_xm, p_ym, pWc1T, pWc2T, pWc3T, nullptr, nullptr, nullptr,
        p_t3, NEDGE, 1225, KCG, TPAD, 2, 2, 1, BIG);
    k_midcon<<<NEDGE, 64>>>(p_ym, p_t3, p_t3 + (size_t)NEDGE * TPAD,
                            p_t3 + 2 * (size_t)NEDGE * TPAD, p_A);

    // 4+5. node_interactions batched
    k_feat<<<2 * NEDGE, 128>>>(x, glovec, wign, eidx, p_feat);
    tgemm<0><<<dim3(1, 64, 4), 256, DYN_SMEM>>>(
        p_feat, nullptr, nullptr, pW1aT, pW2aT, nullptr, nullptr, nullptr, nullptr,
        p_part, 2 * NEDGE, 128, FEATW, 128, 65, 17, 0, 32);
    k_combine<1><<<(2 * NEDGE * 128 + 255) / 256, 256>>>(
        p_part, bn1a, bn2a, nullptr, p_h, 2 * NEDGE, 4, NEDGE);
    tgemm<1><<<dim3(16, 64, 1), 256, DYN_SMEM>>>(
        p_h, nullptr, nullptr, pW1bT, pW2bT, nullptr, bn1b, bn2b, nullptr,
        p_h2, 2 * NEDGE, 2048, 128, 2048, 4, 4, 0, 32);
    k_sh2<<<NEDGE, 128>>>(wign, p_h2, p_sh);

    // 6. fused z-build + rotate
    k_rotmsg<<<NEDGE, 256>>>(x, eidx, p_A, p_sh, wigner, p_msg);

    // 7. edge MLP
    tgemm<0><<<dim3(1, 96, 2), 256, DYN_SMEM>>>(
        p_msg, nullptr, nullptr, pWp1T, nullptr, nullptr, nullptr, nullptr, nullptr,
        p_part, NEDGE * NYR, 128, 2048, 128, 64, 32, 0, BIG);
    k_combine<2><<<(NEDGE * NYR * 128 + 255) / 256, 256>>>(
        p_part, bp1, bp1, p_xe, p_m1, NEDGE * NYR, 2, BIG);
    tgemm<1><<<dim3(16, 96, 1), 256, DYN_SMEM>>>(
        p_m1, nullptr, nullptr, pWp2T, nullptr, nullptr, bp2, nullptr, nullptr,
        p_m2, NEDGE * NYR, 2048, 128, 2048, 4, 4, 0, BIG);

    // 8. NY-mean + inverse rotation
    k_out<<<NEDGE, 256>>>(p_m2, winv, out);
}

// round 10
// speedup vs baseline: 1.3551x; 1.0864x over previous
#include <cuda_runtime.h>
#include <cstdint>
#include <math.h>

// ---------------- problem constants ----------------
#define NNODE 2048
#define NEDGE 4096
#define LF    49
#define LR    16
#define MMID  25
#define NYR   3
#define CCH   128
#define HID   128
#define XLC   (LF*CCH)      // 6272
#define FEATW 2064          // 16*129
#define MSGW  2048          // 16*128
#define TPAD  1280          // padded 1225
#define KCG   64            // padded 49

// ---------------- device scratch ----------------
__device__ __align__(16) float g_WdT  [128*128];
__device__ __align__(16) float g_Wn1aT[128*FEATW];
__device__ __align__(16) float g_Wn1bT[2048*128];
__device__ __align__(16) float g_Wn2aT[128*FEATW];
__device__ __align__(16) float g_Wn2bT[2048*128];
__device__ __align__(16) float g_Wp1T [128*2048];
__device__ __align__(16) float g_Wp2T [2048*128];
__device__ __align__(16) float g_Wc1T [TPAD*KCG];
__device__ __align__(16) float g_Wc2T [TPAD*KCG];
__device__ __align__(16) float g_Wc3T [TPAD*KCG];
__device__ __align__(16) float g_xer  [NEDGE*128];
__device__ __align__(16) float g_xe   [NEDGE*HID];
__device__ __align__(16) float g_xm   [NEDGE*KCG];
__device__ __align__(16) float g_ym   [NEDGE*KCG];
__device__ __align__(16) float g_t3   [3*NEDGE*TPAD];
__device__ __align__(16) float g_A    [NEDGE*LF];
__device__ __align__(16) float g_feat [2*NEDGE*FEATW];
__device__ __align__(16) float g_h    [2*NEDGE*HID];
__device__ __align__(16) float g_h2   [2*NEDGE*MSGW];
__device__ __align__(16) float g_sh   [NEDGE*LR*CCH];
__device__ __align__(16) float g_msg  [NEDGE*NYR*MSGW];
__device__ __align__(16) float g_m1   [NEDGE*NYR*HID];
__device__ __align__(16) float g_m2   [NEDGE*NYR*MSGW];
__device__ __align__(16) float g_part [4*12288*128];

__device__ __forceinline__ float silu_f(float v) { return v / (1.0f + __expf(-v)); }

// round fp32 -> nearest tf32 value (kept in fp32 container)
__device__ __forceinline__ float rtf(float f) {
    uint32_t r;
    asm("cvt.rna.tf32.f32 %0, %1;" : "=r"(r) : "f"(f));
    return __uint_as_float(r);
}

__device__ __forceinline__ void mma8(float* d, uint32_t a0, uint32_t a1, uint32_t a2,
                                     uint32_t a3, uint32_t b0, uint32_t b1) {
    asm volatile(
        "mma.sync.aligned.m16n8k8.row.col.f32.tf32.tf32.f32 "
        "{%0,%1,%2,%3}, {%4,%5,%6,%7}, {%8,%9}, {%0,%1,%2,%3};"
        : "+f"(d[0]), "+f"(d[1]), "+f"(d[2]), "+f"(d[3])
        : "r"(a0), "r"(a1), "r"(a2), "r"(a3), "r"(b0), "r"(b1));
}

__device__ __forceinline__ void cp16(uint32_t dst, const float* src, bool pred) {
    int sz = pred ? 16 : 0;
    asm volatile("cp.async.cg.shared.global [%0], [%1], 16, %2;"
                 :: "r"(dst), "l"(src), "r"(sz) : "memory");
}
#define CP_COMMIT() asm volatile("cp.async.commit_group;" ::: "memory")
template<int N> __device__ __forceinline__ void cpwait() {
    asm volatile("cp.async.wait_group %0;" :: "n"(N) : "memory");
}

// ---------------------------------------------------------------------------
// tf32 mma.sync GEMM, CUTLASS-style tiling: 128 threads, 2x2 warps,
// warp tile 64x64, CTA tile 128x128, K-chunks 32, cp.async double buffer.
// Inputs MUST be tf32-pre-rounded (producers apply cvt.rna).
// zmode=0: grid.z = split-K (C + z*M*ldc); dual-B keyed on blockIdx.y/ysplit.
// zmode=1: grid.z = batch (A/B by z).
// EPI: 0=raw, 1=bias+silu, 2=bias+silu then *= xe[(row/3)*128+col]
// ---------------------------------------------------------------------------
#define LDA 36
#define ATILE (128*LDA)
#define BUFSZ (2*ATILE)
#define DYN_SMEM (2*BUFSZ*4)     // 73728 bytes per CTA; occ 2 -> 147456 < 227KB

template<int EPI>
__global__ __launch_bounds__(128, 2)
void tgemm(const float* __restrict__ A0, const float* __restrict__ A1,
           const float* __restrict__ A2,
           const float* __restrict__ B0, const float* __restrict__ B1,
           const float* __restrict__ B2,
           const float* __restrict__ bias0, const float* __restrict__ bias1,
           const float* __restrict__ xe,
           float* __restrict__ C, int M, int Nreal, int K, int ldc,
           int chunksTotal, int chunksPerZ, int zmode, int ysplit)
{
    extern __shared__ uint32_t sm[];
    const uint32_t smBase = (uint32_t)__cvta_generic_to_shared(sm);
    const int tid  = threadIdx.x;
    const int lane = tid & 31;
    const int warp = tid >> 5;           // 0..3
    const int wm = warp >> 1, wn = warp & 1;
    const int g = lane >> 2, t = lane & 3;

    const int bm0 = blockIdx.y * 128;
    const int bn0 = blockIdx.x * 128;
    const int z   = blockIdx.z;

    const float* A;
    const float* BT;
    const float* bias;
    int c0, cend;
    if (zmode) {
        A    = (z == 0) ? A0 : (z == 1) ? A1 : A2;
        BT   = (z == 0) ? B0 : (z == 1) ? B1 : B2;
        bias = bias0;
        c0 = 0; cend = chunksTotal;
    } else {
        A    = A0;
        BT   = ((int)blockIdx.y < ysplit) ? B0 : B1;
        bias = ((int)blockIdx.y < ysplit) ? bias0 : bias1;
        c0 = z * chunksPerZ;
        cend = c0 + chunksPerZ; if (cend > chunksTotal) cend = chunksTotal;
    }

    float acc[4][8][4];                  // 128 regs: warp tile 64x64
#pragma unroll
    for (int i = 0; i < 4; i++)
#pragma unroll
        for (int j = 0; j < 8; j++)
#pragma unroll
            for (int q = 0; q < 4; q++) acc[i][j][q] = 0.0f;

    const int lseg = tid & 7;

    auto issue = [&](int c, int b) {
        const int kbase = c * 32;
        const int gk = kbase + lseg * 4;
        const bool kok = gk < K;
        uint32_t As = smBase + (uint32_t)(b * BUFSZ) * 4;
        uint32_t Bs = As + ATILE * 4;
#pragma unroll
        for (int i = 0; i < 8; i++) {
            int idx = tid + i * 128;
            int r = idx >> 3;            // seg = idx&7 == lseg (128 % 8 == 0)
            cp16(As + (uint32_t)(r * LDA + lseg * 4) * 4,
                 A + (size_t)(bm0 + r) * K + gk, kok);
        }
#pragma unroll
        for (int i = 0; i < 8; i++) {
            int idx = tid + i * 128;
            int r = idx >> 3;
            int gn = bn0 + r;
            cp16(Bs + (uint32_t)(r * LDA + lseg * 4) * 4,
                 BT + (size_t)gn * K + gk, kok && (gn < Nreal));
        }
        CP_COMMIT();
    };

    issue(c0, 0);
    for (int c = c0; c < cend; ++c) {
        int b = (c - c0) & 1;
        if (c + 1 < cend) { issue(c + 1, b ^ 1); cpwait<1>(); }
        else              { cpwait<0>(); }
        __syncthreads();

        const uint32_t* As = sm + b * BUFSZ;
        const uint32_t* Bs = As + ATILE;
#pragma unroll
        for (int kk = 0; kk < 4; kk++) {
            const int k0 = kk * 8;
            uint32_t af[4][4], bf[8][2];
#pragma unroll
            for (int i = 0; i < 4; i++) {
                int mb = wm * 64 + i * 16;
                af[i][0] = As[(mb + g)     * LDA + k0 + t];
                af[i][1] = As[(mb + g + 8) * LDA + k0 + t];
                af[i][2] = As[(mb + g)     * LDA + k0 + t + 4];
                af[i][3] = As[(mb + g + 8) * LDA + k0 + t + 4];
            }
#pragma unroll
            for (int j = 0; j < 8; j++) {
                int nb = wn * 64 + j * 8;
                bf[j][0] = Bs[(nb + g) * LDA + k0 + t];
                bf[j][1] = Bs[(nb + g) * LDA + k0 + t + 4];
            }
#pragma unroll
            for (int i = 0; i < 4; i++)
#pragma unroll
                for (int j = 0; j < 8; j++)
                    mma8(acc[i][j], af[i][0], af[i][1], af[i][2], af[i][3],
                         bf[j][0], bf[j][1]);
        }
        __syncthreads();   // all warps done reading buf b before it refills (c+2)
    }

    float* Cz = C + (size_t)z * M * ldc;
#pragma unroll
    for (int i = 0; i < 4; i++) {
        int r0 = bm0 + wm * 64 + i * 16 + g;
#pragma unroll
        for (int j = 0; j < 8; j++) {
            int cc = bn0 + wn * 64 + j * 8 + 2 * t;
#pragma unroll
            for (int half = 0; half < 2; half++) {
                int row = r0 + half * 8;
                float v0 = acc[i][j][half * 2 + 0];
                float v1 = acc[i][j][half * 2 + 1];
                if (cc < Nreal) {
                    if (EPI >= 1) {
                        v0 = silu_f(v0 + bias[cc]);
                        v1 = (cc + 1 < Nreal) ? silu_f(v1 + bias[cc + 1]) : 0.0f;
                    }
                    if (EPI == 2) {
                        const float* xr = xe + (size_t)(row / 3) * 128;
                        v0 *= xr[cc];
                        if (cc + 1 < Nreal) v1 *= xr[cc + 1];
                    }
                    float* cp = Cz + (size_t)row * ldc + cc;
                    if (cc + 1 < Nreal) { float2 fv = make_float2(v0, v1); *(float2*)cp = fv; }
                    else cp[0] = v0;
                }
            }
        }
    }
}

// combine split-K partials: out = epi(sum_z part[z] + bias), tf32-rounded
// (outputs feed the next GEMM). bias1 used for rows >= Mhalf.
template<int EPI>
__global__ void k_combine(const float* __restrict__ part, const float* __restrict__ bias0,
                          const float* __restrict__ bias1, const float* __restrict__ xe,
                          float* __restrict__ outp, int M, int nsplit, int Mhalf)
{
    int idx = blockIdx.x * 256 + threadIdx.x;
    if (idx >= M * 128) return;
    int m = idx >> 7, n = idx & 127;
    float s = (m < Mhalf) ? bias0[n] : bias1[n];
    for (int zz = 0; zz < nsplit; zz++) s += part[(size_t)zz * M * 128 + idx];
    s = silu_f(s);
    if (EPI == 2) s *= xe[(size_t)(m / 3) * 128 + n];
    outp[idx] = rtf(s);
}

// tf32-round a buffer (external GEMM inputs)
__global__ void k_round(const float* __restrict__ src, float* __restrict__ dst, int n)
{
    int i = blockIdx.x * 256 + threadIdx.x;
    if (i < n) dst[i] = rtf(src[i]);
}

// ---------------- fused multi-transpose (tf32-rounded output) ----------------
struct TD { const float* src; float* dst; int R, C, ldD, tilesX, tileOff; };
struct TDPack { TD d[10]; };

__global__ void k_tmulti(TDPack P, int ndesc)
{
    __shared__ float smt[32][33];
    int bid = blockIdx.x;
    int di = 0;
    for (int i = 1; i < ndesc; i++) if (bid >= P.d[i].tileOff) di = i;
    const TD& D = P.d[di];
    int ti = bid - D.tileOff;
    int c0 = (ti % D.tilesX) * 32;
    int r0 = (ti / D.tilesX) * 32;
    int tx = threadIdx.x & 31, ty = threadIdx.x >> 5;
#pragma unroll
    for (int i = 0; i < 4; i++) {
        int r = r0 + ty + i * 8, c = c0 + tx;
        smt[ty + i * 8][tx] = (r < D.R && c < D.C) ? rtf(D.src[(size_t)r * D.C + c]) : 0.0f;
    }
    __syncthreads();
#pragma unroll
    for (int i = 0; i < 4; i++) {
        int c = c0 + ty + i * 8, r = r0 + tx;
        if (c < D.C && r < D.ldD) D.dst[(size_t)c * D.ldD + r] = smt[tx][ty + i * 8];
    }
}

// ---------------------------------------------------------------------------
// per-edge kernels (R9-proven; GEMM-feeding outputs tf32-rounded as in R8)
// ---------------------------------------------------------------------------
__global__ void k_xmym(const float* __restrict__ x, const int* __restrict__ eidx,
                       float* __restrict__ xm, float* __restrict__ ym)
{
    int e = blockIdx.x, tid = threadIdx.x;
    int lane = tid & 31, warp = tid >> 5;
    int src = eidx[e], dst = eidx[NEDGE + e];
    const float4* ps = (const float4*)(x + (size_t)src * XLC);
    const float4* pt = (const float4*)(x + (size_t)dst * XLC);
    if (tid >= 49 && tid < 64) { xm[e * KCG + tid] = 0.f; ym[e * KCG + tid] = 0.f; }
    for (int l = warp; l < LF; l += 4) {
        float4 a = ps[l * 32 + lane];
        float4 b = pt[l * 32 + lane];
        float s = (a.x + a.y) + (a.z + a.w);
        float u = (b.x + b.y) + (b.z + b.w);
#pragma unroll
        for (int o = 16; o > 0; o >>= 1) {
            s += __shfl_xor_sync(0xffffffffu, s, o);
            u += __shfl_xor_sync(0xffffffffu, u, o);
        }
        if (lane == 0) {
            xm[e * KCG + l] = rtf(s * (1.0f / 128.0f));
            ym[e * KCG + l] = rtf(u * (1.0f / 128.0f));
        }
    }
}

// merged: mid[o] = sum_j ym[j]*t1[j*25+o]; A[o] = sum_j mid[j]*(t2+t3)[j*49+o]
__global__ void k_midcon(const float* __restrict__ ym, const float* __restrict__ t1,
                         const float* __restrict__ t2, const float* __restrict__ t3,
                         float* __restrict__ Aout)
{
    int e = blockIdx.x, tid = threadIdx.x;   // 64 threads
    __shared__ float ys[LF];
    __shared__ float ms[MMID];
    if (tid < LF) ys[tid] = ym[e * KCG + tid];
    __syncthreads();
    if (tid < MMID) {
        const float* tp = t1 + (size_t)e * TPAD + tid;
        float s = 0.0f;
#pragma unroll
        for (int j = 0; j < LF; j++) s = fmaf(ys[j], tp[j * MMID], s);
        ms[tid] = s;
    }
    __syncthreads();
    if (tid < LF) {
        const float* tp2 = t2 + (size_t)e * TPAD + tid;
        const float* tp3 = t3 + (size_t)e * TPAD + tid;
        float s = 0.0f;
#pragma unroll
        for (int j = 0; j < MMID; j++)
            s = fmaf(ms[j], tp2[j * LF] + tp3[j * LF], s);
        Aout[e * LF + tid] = s;
    }
}

// batched: blocks 0..4095 -> (node=src, other=dst); 4096..8191 -> swapped
__global__ void k_feat(const float* __restrict__ x, const float* __restrict__ glovec,
                       const float* __restrict__ wign, const int* __restrict__ eidx,
                       float* __restrict__ feat)
{
    int e2 = blockIdx.x, tid = threadIdx.x;
    int half = e2 >> 12;
    int e = e2 & 4095;
    __shared__ float wigS[256];
    __shared__ float gS[16];
    __shared__ float red[64];
    int node  = eidx[half ? (NEDGE + e) : e];
    int other = eidx[half ? e : (NEDGE + e)];
    wigS[tid]       = wign[e * 256 + tid];
    wigS[tid + 128] = wign[e * 256 + 128 + tid];
    if (tid < 16) gS[tid] = glovec[other * LR + tid];
    __syncthreads();

    float xr[16];
    const float* xp = x + (size_t)node * XLC;
#pragma unroll
    for (int j = 0; j < 16; j++) xr[j] = xp[j * 128 + tid];

    int lane = tid & 31, warp = tid >> 5;
    float* fp = feat + (size_t)e2 * FEATW;
#pragma unroll
    for (int i = 0; i < 16; i++) {
        float a = 0.0f;
#pragma unroll
        for (int j = 0; j < 16; j++) a = fmaf(wigS[j * 16 + i], xr[j], a);
        fp[i * 129 + tid] = rtf(a);
        float s = a;
#pragma unroll
        for (int o = 16; o > 0; o >>= 1) s += __shfl_xor_sync(0xffffffffu, s, o);
        if (lane == 0) red[i * 4 + warp] = s;
    }
    __syncthreads();
    if (tid < 16) {
        float s = red[tid * 4] + red[tid * 4 + 1] + red[tid * 4 + 2] + red[tid * 4 + 3];
        fp[tid * 129 + 128] = rtf(s * (1.0f / 128.0f) * gS[tid]);
    }
}

// sh[e] = wig_node[e] @ (h2[e] + h2[e+4096])
__global__ void k_sh2(const float* __restrict__ wign, const float* __restrict__ h2,
                      float* __restrict__ sh)
{
    int e = blockIdx.x, tid = threadIdx.x;
    __shared__ float wigS[256];
    wigS[tid]       = wign[e * 256 + tid];
    wigS[tid + 128] = wign[e * 256 + 128 + tid];
    __syncthreads();
    float hr[16];
    const float* hpa = h2 + (size_t)e * MSGW;
    const float* hpb = h2 + (size_t)(e + NEDGE) * MSGW;
#pragma unroll
    for (int j = 0; j < 16; j++) hr[j] = hpa[j * 128 + tid] + hpb[j * 128 + tid];
    float* sp = sh + (size_t)e * MSGW;
#pragma unroll
    for (int i = 0; i < 16; i++) {
        float s = 0.0f;
#pragma unroll
        for (int j = 0; j < 16; j++) s = fmaf(wigS[i * 16 + j], hr[j], s);
        sp[i * 128 + tid] = s;
    }
}

__global__ __launch_bounds__(256)
void k_rotmsg(const float* __restrict__ x, const int* __restrict__ eidx,
              const float* __restrict__ Aarr, const float* __restrict__ sh,
              const float* __restrict__ wigner, float* __restrict__ msg)
{
    int e = blockIdx.x, tid = threadIdx.x;
    __shared__ float zs[LF * 128];
    __shared__ float wgS[48 * 49];
    __shared__ float As_[LF];
    int src = eidx[e], dst = eidx[NEDGE + e];
    const float4* xs4 = (const float4*)(x + (size_t)src * XLC);
    const float4* xt4 = (const float4*)(x + (size_t)dst * XLC);
    const float4* sh4 = (const float4*)(sh + (size_t)e * MSGW);
    if (tid < LF) As_[tid] = Aarr[e * LF + tid];
    __syncthreads();
    float4* zs4 = (float4*)zs;
    for (int i4 = tid; i4 < LF * 32; i4 += 256) {
        int l = i4 >> 5;
        float4 a = xs4[i4], b = xt4[i4];
        float al = As_[l];
        float4 v;
        v.x = 2.0f * (a.x + b.x) + al;
        v.y = 2.0f * (a.y + b.y) + al;
        v.z = 2.0f * (a.z + b.z) + al;
        v.w = 2.0f * (a.w + b.w) + al;
        if (l < 16) {
            float4 s = sh4[i4];
            v.x += s.x; v.y += s.y; v.z += s.z; v.w += s.w;
        }
        zs4[i4] = v;
    }
    const float4* wp4 = (const float4*)(wigner + (size_t)e * (48 * 49));
    float4* wg4 = (float4*)wgS;
    for (int i4 = tid; i4 < 588; i4 += 256) wg4[i4] = wp4[i4];
    __syncthreads();

    int cg = tid & 63, grp = tid >> 6;
    float2 acc[12];
#pragma unroll
    for (int rr = 0; rr < 12; rr++) { acc[rr].x = 0.0f; acc[rr].y = 0.0f; }
    const float2* z2 = (const float2*)zs;
    for (int l = 0; l < LF; l++) {
        float2 zv = z2[l * 64 + cg];
#pragma unroll
        for (int rr = 0; rr < 12; rr++) {
            float w = wgS[(grp * 12 + rr) * LF + l];
            acc[rr].x = fmaf(w, zv.x, acc[rr].x);
            acc[rr].y = fmaf(w, zv.y, acc[rr].y);
        }
    }
    float* mp = msg + (size_t)e * (NYR * MSGW);
#pragma unroll
    for (int rr = 0; rr < 12; rr++) {
        int row = grp * 12 + rr;
        float2 o; o.x = rtf(acc[rr].x); o.y = rtf(acc[rr].y);
        ((float2*)(mp + row * 128))[cg] = o;
    }
}

__global__ __launch_bounds__(256)
void k_out(const float* __restrict__ m2, const float* __restrict__ winv,
           float* __restrict__ out)
{
    int e = blockIdx.x, tid = threadIdx.x;
    __shared__ float mmS[16 * 128];
    __shared__ float wvS[LF * 16];
    const float4* mp4 = (const float4*)(m2 + (size_t)e * (NYR * MSGW));
    float4* mm4 = (float4*)mmS;
    for (int i4 = tid; i4 < 512; i4 += 256) {
        float4 a = mp4[i4], b = mp4[i4 + 512], c = mp4[i4 + 1024];
        float4 v;
        v.x = (a.x + b.x + c.x) * (1.0f / 3.0f);
        v.y = (a.y + b.y + c.y) * (1.0f / 3.0f);
        v.z = (a.z + b.z + c.z) * (1.0f / 3.0f);
        v.w = (a.w + b.w + c.w) * (1.0f / 3.0f);
        mm4[i4] = v;
    }
    const float4* wp4 = (const float4*)(winv + (size_t)e * (LF * 16));
    float4* wv4 = (float4*)wvS;
    for (int i4 = tid; i4 < 196; i4 += 256) wv4[i4] = wp4[i4];
    __syncthreads();

    const float INV3 = 0.5773502691896258f;
    int cg = tid & 63, grp = tid >> 6;
    const float2* mm2 = (const float2*)mmS;
    float* op = out + (size_t)e * XLC;
    for (int b = grp; b < LF; b += 4) {
        float2 s; s.x = 0.0f; s.y = 0.0f;
#pragma unroll
        for (int r = 0; r < 16; r++) {
            float w = wvS[b * 16 + r];
            float2 mv = mm2[r * 64 + cg];
            s.x = fmaf(w, mv.x, s.x);
            s.y = fmaf(w, mv.y, s.y);
        }
        s.x *= INV3; s.y *= INV3;
        ((float2*)(op + b * 128))[cg] = s;
    }
}

// ---------------------------------------------------------------------------
extern "C" void kernel_launch(void* const* d_in, const int* in_sizes, int n_in,
                              void* d_out, int out_size)
{
    const float* x      = (const float*)d_in[0];
    const float* glovec = (const float*)d_in[2];
    const float* x_edge = (const float*)d_in[3];
    const int*   eidx   = (const int*)  d_in[4];
    const float* W_cg1  = (const float*)d_in[8];
    const float* W_cg21 = (const float*)d_in[9];
    const float* W_cg22 = (const float*)d_in[10];
    const float* Wn1a   = (const float*)d_in[11];
    const float* bn1a   = (const float*)d_in[12];
    const float* Wn1b   = (const float*)d_in[13];
    const float* bn1b   = (const float*)d_in[14];
    const float* Wn2a   = (const float*)d_in[15];
    const float* bn2a   = (const float*)d_in[16];
    const float* Wn2b   = (const float*)d_in[17];
    const float* bn2b   = (const float*)d_in[18];
    const float* Wd     = (const float*)d_in[19];
    const float* bd     = (const float*)d_in[20];
    const float* Wp1    = (const float*)d_in[21];
    const float* bp1    = (const float*)d_in[22];
    const float* Wp2    = (const float*)d_in[23];
    const float* bp2    = (const float*)d_in[24];
    const float* wigner = (const float*)d_in[25];
    const float* winv   = (const float*)d_in[26];
    const float* wign   = (const float*)d_in[27];
    float* out = (float*)d_out;

    float *pWdT, *pW1aT, *pW1bT, *pW2aT, *pW2bT, *pWp1T, *pWp2T, *pWc1T, *pWc2T, *pWc3T;
    float *p_xer, *p_xe, *p_xm, *p_ym, *p_t3, *p_A, *p_feat, *p_h, *p_h2,
          *p_sh, *p_msg, *p_m1, *p_m2, *p_part;
    cudaGetSymbolAddress((void**)&pWdT,  g_WdT);
    cudaGetSymbolAddress((void**)&pW1aT, g_Wn1aT);
    cudaGetSymbolAddress((void**)&pW1bT, g_Wn1bT);
    cudaGetSymbolAddress((void**)&pW2aT, g_Wn2aT);
    cudaGetSymbolAddress((void**)&pW2bT, g_Wn2bT);
    cudaGetSymbolAddress((void**)&pWp1T, g_Wp1T);
    cudaGetSymbolAddress((void**)&pWp2T, g_Wp2T);
    cudaGetSymbolAddress((void**)&pWc1T, g_Wc1T);
    cudaGetSymbolAddress((void**)&pWc2T, g_Wc2T);
    cudaGetSymbolAddress((void**)&pWc3T, g_Wc3T);
    cudaGetSymbolAddress((void**)&p_xer,  g_xer);
    cudaGetSymbolAddress((void**)&p_xe,   g_xe);
    cudaGetSymbolAddress((void**)&p_xm,   g_xm);
    cudaGetSymbolAddress((void**)&p_ym,   g_ym);
    cudaGetSymbolAddress((void**)&p_t3,   g_t3);
    cudaGetSymbolAddress((void**)&p_A,    g_A);
    cudaGetSymbolAddress((void**)&p_feat, g_feat);
    cudaGetSymbolAddress((void**)&p_h,    g_h);
    cudaGetSymbolAddress((void**)&p_h2,   g_h2);
    cudaGetSymbolAddress((void**)&p_sh,   g_sh);
    cudaGetSymbolAddress((void**)&p_msg,  g_msg);
    cudaGetSymbolAddress((void**)&p_m1,   g_m1);
    cudaGetSymbolAddress((void**)&p_m2,   g_m2);
    cudaGetSymbolAddress((void**)&p_part, g_part);

    cudaFuncSetAttribute(tgemm<0>, cudaFuncAttributeMaxDynamicSharedMemorySize, DYN_SMEM);
    cudaFuncSetAttribute(tgemm<1>, cudaFuncAttributeMaxDynamicSharedMemorySize, DYN_SMEM);
    cudaFuncSetAttribute(tgemm<2>, cudaFuncAttributeMaxDynamicSharedMemorySize, DYN_SMEM);

    const int BIG = 1 << 30;

    // ---- weight transposes (tf32-rounded) in ONE launch + x_edge rounding ----
    {
        TDPack P;
        auto set = [&](int i, const float* s, float* dst, int R, int C, int ldD, int& off) {
            int tx = (C + 31) / 32, ty = (ldD + 31) / 32;
            P.d[i] = TD{ s, dst, R, C, ldD, tx, off };
            off += tx * ty;
        };
        int off = 0;
        set(0, Wd,    pWdT,  128,  128,  128,  off);
        set(1, Wn1a,  pW1aT, FEATW,128,  FEATW,off);
        set(2, Wn1b,  pW1bT, 128,  2048, 128,  off);
        set(3, Wn2a,  pW2aT, FEATW,128,  FEATW,off);
        set(4, Wn2b,  pW2bT, 128,  2048, 128,  off);
        set(5, Wp1,   pWp1T, 2048, 128,  2048, off);
        set(6, Wp2,   pWp2T, 128,  2048, 128,  off);
        set(7, W_cg1, pWc1T, 49,   1225, KCG,  off);
        set(8, W_cg21,pWc2T, 49,   1225, KCG,  off);
        set(9, W_cg22,pWc3T, 49,   1225, KCG,  off);
        k_tmulti<<<off, 256>>>(P, 10);
    }
    k_round<<<(NEDGE * 128 + 255) / 256, 256>>>(x_edge, p_xer, NEDGE * 128);

    // 1. xe = silu(x_edge @ Wd + bd)
    tgemm<1><<<dim3(1, 32, 1), 128, DYN_SMEM>>>(
        p_xer, nullptr, nullptr, pWdT, nullptr, nullptr, bd, nullptr, nullptr,
        p_xe, NEDGE, 128, 128, 128, 4, 4, 0, BIG);

    // 2. channel means (K padded to 64)
    k_xmym<<<NEDGE, 128>>>(x, eidx, p_xm, p_ym);

    // 3. CG bilinears: batched z=3, then fused mid+contract
    tgemm<0><<<dim3(10, 32, 3), 128, DYN_SMEM>>>(
        p_xm, p_xm, p_ym, pWc1T, pWc2T, pWc3T, nullptr, nullptr, nullptr,
        p_t3, NEDGE, 1225, KCG, TPAD, 2, 2, 1, BIG);
    k_midcon<<<NEDGE, 64>>>(p_ym, p_t3, p_t3 + (size_t)NEDGE * TPAD,
                            p_t3 + 2 * (size_t)NEDGE * TPAD, p_A);

    // 4+5. node_interactions batched
    k_feat<<<2 * NEDGE, 128>>>(x, glovec, wign, eidx, p_feat);
    tgemm<0><<<dim3(1, 64, 4), 128, DYN_SMEM>>>(
        p_feat, nullptr, nullptr, pW1aT, pW2aT, nullptr, nullptr, nullptr, nullptr,
        p_part, 2 * NEDGE, 128, FEATW, 128, 65, 17, 0, 32);
    k_combine<1><<<(2 * NEDGE * 128 + 255) / 256, 256>>>(
        p_part, bn1a, bn2a, nullptr, p_h, 2 * NEDGE, 4, NEDGE);
    tgemm<1><<<dim3(16, 64, 1), 128, DYN_SMEM>>>(
        p_h, nullptr, nullptr, pW1bT, pW2bT, nullptr, bn1b, bn2b, nullptr,
        p_h2, 2 * NEDGE, 2048, 128, 2048, 4, 4, 0, 32);
    k_sh2<<<NEDGE, 128>>>(wign, p_h2, p_sh);

    // 6. fused z-build + rotate (msg tf32-rounded for Wp1 GEMM)
    k_rotmsg<<<NEDGE, 256>>>(x, eidx, p_A, p_sh, wigner, p_msg);

    // 7. edge MLP
    tgemm<0><<<dim3(1, 96, 2), 128, DYN_SMEM>>>(
        p_msg, nullptr, nullptr, pWp1T, nullptr, nullptr, nullptr, nullptr, nullptr,
        p_part, NEDGE * NYR, 128, 2048, 128, 64, 32, 0, BIG);
    k_combine<2><<<(NEDGE * NYR * 128 + 255) / 256, 256>>>(
        p_part, bp1, bp1, p_xe, p_m1, NEDGE * NYR, 2, BIG);
    tgemm<1><<<dim3(16, 96, 1), 128, DYN_SMEM>>>(
        p_m1, nullptr, nullptr, pWp2T, nullptr, nullptr, bp2, nullptr, nullptr,
        p_m2, NEDGE * NYR, 2048, 128, 2048, 4, 4, 0, BIG);

    // 8. NY-mean + inverse rotation
    k_out<<<NEDGE, 256>>>(p_m2, winv, out);
}

// round 11
// speedup vs baseline: 1.3713x; 1.0120x over previous
#include <cuda_runtime.h>
#include <cstdint>
#include <math.h>

// ---------------- problem constants ----------------
#define NNODE 2048
#define NEDGE 4096
#define LF    49
#define LR    16
#define MMID  25
#define NYR   3
#define CCH   128
#define HID   128
#define XLC   (LF*CCH)      // 6272
#define FEATW 2064          // 16*129
#define MSGW  2048          // 16*128
#define TPAD  1280          // padded 1225
#define KCG   64            // padded 49

// ---------------- device scratch ----------------
__device__ __align__(16) float g_WdT  [128*128];
__device__ __align__(16) float g_Wn1aT[128*FEATW];
__device__ __align__(16) float g_Wn1bT[2048*128];
__device__ __align__(16) float g_Wn2aT[128*FEATW];
__device__ __align__(16) float g_Wn2bT[2048*128];
__device__ __align__(16) float g_Wp1T [128*2048];
__device__ __align__(16) float g_Wp2T [2048*128];
__device__ __align__(16) float g_Wc1T [TPAD*KCG];
__device__ __align__(16) float g_Wc2T [TPAD*KCG];
__device__ __align__(16) float g_Wc3T [TPAD*KCG];
__device__ __align__(16) float g_xer  [NEDGE*128];
__device__ __align__(16) float g_xe   [NEDGE*HID];
__device__ __align__(16) float g_nm   [NNODE*KCG];
__device__ __align__(16) float g_xm   [NEDGE*KCG];
__device__ __align__(16) float g_ym   [NEDGE*KCG];
__device__ __align__(16) float g_t3   [3*NEDGE*TPAD];
__device__ __align__(16) float g_A    [NEDGE*LF];
__device__ __align__(16) float g_feat [2*NEDGE*FEATW];
__device__ __align__(16) float g_h    [2*NEDGE*HID];
__device__ __align__(16) float g_h2   [2*NEDGE*MSGW];
__device__ __align__(16) float g_msg  [NEDGE*NYR*MSGW];
__device__ __align__(16) float g_m1   [NEDGE*NYR*HID];
__device__ __align__(16) float g_m2   [NEDGE*NYR*MSGW];
__device__ __align__(16) float g_part [4*12288*128];

__device__ __forceinline__ float silu_f(float v) { return v / (1.0f + __expf(-v)); }

// round fp32 -> nearest tf32 value (kept in fp32 container)
__device__ __forceinline__ float rtf(float f) {
    uint32_t r;
    asm("cvt.rna.tf32.f32 %0, %1;" : "=r"(r) : "f"(f));
    return __uint_as_float(r);
}

__device__ __forceinline__ void mma8(float* d, uint32_t a0, uint32_t a1, uint32_t a2,
                                     uint32_t a3, uint32_t b0, uint32_t b1) {
    asm volatile(
        "mma.sync.aligned.m16n8k8.row.col.f32.tf32.tf32.f32 "
        "{%0,%1,%2,%3}, {%4,%5,%6,%7}, {%8,%9}, {%0,%1,%2,%3};"
        : "+f"(d[0]), "+f"(d[1]), "+f"(d[2]), "+f"(d[3])
        : "r"(a0), "r"(a1), "r"(a2), "r"(a3), "r"(b0), "r"(b1));
}

__device__ __forceinline__ void cp16(uint32_t dst, const float* src, bool pred) {
    int sz = pred ? 16 : 0;
    asm volatile("cp.async.cg.shared.global [%0], [%1], 16, %2;"
                 :: "r"(dst), "l"(src), "r"(sz) : "memory");
}
#define CP_COMMIT() asm volatile("cp.async.commit_group;" ::: "memory")
template<int N> __device__ __forceinline__ void cpwait() {
    asm volatile("cp.async.wait_group %0;" :: "n"(N) : "memory");
}

// ---------------------------------------------------------------------------
// tf32 mma.sync GEMM: 128 threads, 2x2 warps, warp tile 64x64, CTA 128x128,
// K-chunks 32, cp.async double buffer, kk-software-pipelined fragment loads.
// Inputs MUST be tf32-pre-rounded.
// zmode=0: grid.z = split-K (C + z*M*ldc); dual-B keyed on blockIdx.y/ysplit.
// zmode=1: grid.z = batch (A/B by z).
// EPI: 0=raw, 1=bias+silu, 2=bias+silu then *= xe[(row/3)*128+col]
// ---------------------------------------------------------------------------
#define LDA 36
#define ATILE (128*LDA)
#define BUFSZ (2*ATILE)
#define DYN_SMEM (2*BUFSZ*4)     // 73728 bytes per CTA; occ 2

template<int EPI>
__global__ __launch_bounds__(128, 2)
void tgemm(const float* __restrict__ A0, const float* __restrict__ A1,
           const float* __restrict__ A2,
           const float* __restrict__ B0, const float* __restrict__ B1,
           const float* __restrict__ B2,
           const float* __restrict__ bias0, const float* __restrict__ bias1,
           const float* __restrict__ xe,
           float* __restrict__ C, int M, int Nreal, int K, int ldc,
           int chunksTotal, int chunksPerZ, int zmode, int ysplit)
{
    extern __shared__ uint32_t sm[];
    const uint32_t smBase = (uint32_t)__cvta_generic_to_shared(sm);
    const int tid  = threadIdx.x;
    const int lane = tid & 31;
    const int warp = tid >> 5;           // 0..3
    const int wm = warp >> 1, wn = warp & 1;
    const int g = lane >> 2, t = lane & 3;

    const int bm0 = blockIdx.y * 128;
    const int bn0 = blockIdx.x * 128;
    const int z   = blockIdx.z;

    const float* A;
    const float* BT;
    const float* bias;
    int c0, cend;
    if (zmode) {
        A    = (z == 0) ? A0 : (z == 1) ? A1 : A2;
        BT   = (z == 0) ? B0 : (z == 1) ? B1 : B2;
        bias = bias0;
        c0 = 0; cend = chunksTotal;
    } else {
        A    = A0;
        BT   = ((int)blockIdx.y < ysplit) ? B0 : B1;
        bias = ((int)blockIdx.y < ysplit) ? bias0 : bias1;
        c0 = z * chunksPerZ;
        cend = c0 + chunksPerZ; if (cend > chunksTotal) cend = chunksTotal;
    }

    float acc[4][8][4];                  // warp tile 64x64
#pragma unroll
    for (int i = 0; i < 4; i++)
#pragma unroll
        for (int j = 0; j < 8; j++)
#pragma unroll
            for (int q = 0; q < 4; q++) acc[i][j][q] = 0.0f;

    const int lseg = tid & 7;

    auto issue = [&](int c, int b) {
        const int kbase = c * 32;
        const int gk = kbase + lseg * 4;
        const bool kok = gk < K;
        uint32_t As = smBase + (uint32_t)(b * BUFSZ) * 4;
        uint32_t Bs = As + ATILE * 4;
#pragma unroll
        for (int i = 0; i < 8; i++) {
            int idx = tid + i * 128;
            int r = idx >> 3;
            cp16(As + (uint32_t)(r * LDA + lseg * 4) * 4,
                 A + (size_t)(bm0 + r) * K + gk, kok);
        }
#pragma unroll
        for (int i = 0; i < 8; i++) {
            int idx = tid + i * 128;
            int r = idx >> 3;
            int gn = bn0 + r;
            cp16(Bs + (uint32_t)(r * LDA + lseg * 4) * 4,
                 BT + (size_t)gn * K + gk, kok && (gn < Nreal));
        }
        CP_COMMIT();
    };

    issue(c0, 0);
    for (int c = c0; c < cend; ++c) {
        int b = (c - c0) & 1;
        if (c + 1 < cend) { issue(c + 1, b ^ 1); cpwait<1>(); }
        else              { cpwait<0>(); }
        __syncthreads();

        const uint32_t* As = sm + b * BUFSZ;
        const uint32_t* Bs = As + ATILE;

        uint32_t af[2][4][4], bf[2][8][2];
        auto loadfrag = [&](int kk, int buf) {
            const int k0 = kk * 8;
#pragma unroll
            for (int i = 0; i < 4; i++) {
                int mb = wm * 64 + i * 16;
                af[buf][i][0] = As[(mb + g)     * LDA + k0 + t];
                af[buf][i][1] = As[(mb + g + 8) * LDA + k0 + t];
                af[buf][i][2] = As[(mb + g)     * LDA + k0 + t + 4];
                af[buf][i][3] = As[(mb + g + 8) * LDA + k0 + t + 4];
            }
#pragma unroll
            for (int j = 0; j < 8; j++) {
                int nb = wn * 64 + j * 8;
                bf[buf][j][0] = Bs[(nb + g) * LDA + k0 + t];
                bf[buf][j][1] = Bs[(nb + g) * LDA + k0 + t + 4];
            }
        };

        loadfrag(0, 0);
#pragma unroll
        for (int kk = 0; kk < 4; kk++) {
            int cur = kk & 1;
            if (kk < 3) loadfrag(kk + 1, cur ^ 1);
#pragma unroll
            for (int i = 0; i < 4; i++)
#pragma unroll
                for (int j = 0; j < 8; j++)
                    mma8(acc[i][j], af[cur][i][0], af[cur][i][1],
                         af[cur][i][2], af[cur][i][3],
                         bf[cur][j][0], bf[cur][j][1]);
        }
        __syncthreads();   // all warps done reading buf b before refill (c+2)
    }

    float* Cz = C + (size_t)z * M * ldc;
#pragma unroll
    for (int i = 0; i < 4; i++) {
        int r0 = bm0 + wm * 64 + i * 16 + g;
#pragma unroll
        for (int j = 0; j < 8; j++) {
            int cc = bn0 + wn * 64 + j * 8 + 2 * t;
#pragma unroll
            for (int half = 0; half < 2; half++) {
                int row = r0 + half * 8;
                float v0 = acc[i][j][half * 2 + 0];
                float v1 = acc[i][j][half * 2 + 1];
                if (cc < Nreal) {
                    if (EPI >= 1) {
                        v0 = silu_f(v0 + bias[cc]);
                        v1 = (cc + 1 < Nreal) ? silu_f(v1 + bias[cc + 1]) : 0.0f;
                    }
                    if (EPI == 2) {
                        const float* xr = xe + (size_t)(row / 3) * 128;
                        v0 *= xr[cc];
                        if (cc + 1 < Nreal) v1 *= xr[cc + 1];
                    }
                    float* cp = Cz + (size_t)row * ldc + cc;
                    if (cc + 1 < Nreal) { float2 fv = make_float2(v0, v1); *(float2*)cp = fv; }
                    else cp[0] = v0;
                }
            }
        }
    }
}

// combine split-K partials: out = epi(sum_z part[z] + bias), tf32-rounded.
template<int EPI>
__global__ void k_combine(const float* __restrict__ part, const float* __restrict__ bias0,
                          const float* __restrict__ bias1, const float* __restrict__ xe,
                          float* __restrict__ outp, int M, int nsplit, int Mhalf)
{
    int idx = blockIdx.x * 256 + threadIdx.x;
    if (idx >= M * 128) return;
    int m = idx >> 7, n = idx & 127;
    float s = (m < Mhalf) ? bias0[n] : bias1[n];
    for (int zz = 0; zz < nsplit; zz++) s += part[(size_t)zz * M * 128 + idx];
    s = silu_f(s);
    if (EPI == 2) s *= xe[(size_t)(m / 3) * 128 + n];
    outp[idx] = rtf(s);
}

// tf32-round a buffer
__global__ void k_round(const float* __restrict__ src, float* __restrict__ dst, int n)
{
    int i = blockIdx.x * 256 + threadIdx.x;
    if (i < n) dst[i] = rtf(src[i]);
}

// ---------------- fused multi-transpose (tf32-rounded output) ----------------
struct TD { const float* src; float* dst; int R, C, ldD, tilesX, tileOff; };
struct TDPack { TD d[10]; };

__global__ void k_tmulti(TDPack P, int ndesc)
{
    __shared__ float smt[32][33];
    int bid = blockIdx.x;
    int di = 0;
    for (int i = 1; i < ndesc; i++) if (bid >= P.d[i].tileOff) di = i;
    const TD& D = P.d[di];
    int ti = bid - D.tileOff;
    int c0 = (ti % D.tilesX) * 32;
    int r0 = (ti / D.tilesX) * 32;
    int tx = threadIdx.x & 31, ty = threadIdx.x >> 5;
#pragma unroll
    for (int i = 0; i < 4; i++) {
        int r = r0 + ty + i * 8, c = c0 + tx;
        smt[ty + i * 8][tx] = (r < D.R && c < D.C) ? rtf(D.src[(size_t)r * D.C + c]) : 0.0f;
    }
    __syncthreads();
#pragma unroll
    for (int i = 0; i < 4; i++) {
        int c = c0 + ty + i * 8, r = r0 + tx;
        if (c < D.C && r < D.ldD) D.dst[(size_t)c * D.ldD + r] = smt[tx][ty + i * 8];
    }
}

// ---------------------------------------------------------------------------
// per-edge kernels
// ---------------------------------------------------------------------------
// per-NODE channel means (replaces per-edge recompute)
__global__ void k_nodemean(const float* __restrict__ x, float* __restrict__ nm)
{
    int n = blockIdx.x, tid = threadIdx.x;
    int lane = tid & 31, warp = tid >> 5;
    const float4* p = (const float4*)(x + (size_t)n * XLC);
    if (tid >= 49 && tid < 64) nm[n * KCG + tid] = 0.f;
    for (int l = warp; l < LF; l += 4) {
        float4 a = p[l * 32 + lane];
        float s = (a.x + a.y) + (a.z + a.w);
#pragma unroll
        for (int o = 16; o > 0; o >>= 1)
            s += __shfl_xor_sync(0xffffffffu, s, o);
        if (lane == 0) nm[n * KCG + l] = rtf(s * (1.0f / 128.0f));
    }
}

// gather node means to edges
__global__ void k_gather(const float* __restrict__ nm, const int* __restrict__ eidx,
                         float* __restrict__ xm, float* __restrict__ ym)
{
    int idx = blockIdx.x * 256 + threadIdx.x;
    if (idx >= NEDGE * KCG) return;
    int e = idx >> 6, tt = idx & 63;
    xm[idx] = nm[eidx[e] * KCG + tt];
    ym[idx] = nm[eidx[NEDGE + e] * KCG + tt];
}

// merged: mid[o] = sum_j ym[j]*t1[j*25+o]; A[o] = sum_j mid[j]*(t2+t3)[j*49+o]
__global__ void k_midcon(const float* __restrict__ ym, const float* __restrict__ t1,
                         const float* __restrict__ t2, const float* __restrict__ t3,
                         float* __restrict__ Aout)
{
    int e = blockIdx.x, tid = threadIdx.x;   // 64 threads
    __shared__ float ys[LF];
    __shared__ float ms[MMID];
    if (tid < LF) ys[tid] = ym[e * KCG + tid];
    __syncthreads();
    if (tid < MMID) {
        const float* tp = t1 + (size_t)e * TPAD + tid;
        float s = 0.0f;
#pragma unroll
        for (int j = 0; j < LF; j++) s = fmaf(ys[j], tp[j * MMID], s);
        ms[tid] = s;
    }
    __syncthreads();
    if (tid < LF) {
        const float* tp2 = t2 + (size_t)e * TPAD + tid;
        const float* tp3 = t3 + (size_t)e * TPAD + tid;
        float s = 0.0f;
#pragma unroll
        for (int j = 0; j < MMID; j++)
            s = fmaf(ms[j], tp2[j * LF] + tp3[j * LF], s);
        Aout[e * LF + tid] = s;
    }
}

// batched: blocks 0..4095 -> (node=src, other=dst); 4096..8191 -> swapped
__global__ void k_feat(const float* __restrict__ x, const float* __restrict__ glovec,
                       const float* __restrict__ wign, const int* __restrict__ eidx,
                       float* __restrict__ feat)
{
    int e2 = blockIdx.x, tid = threadIdx.x;
    int half = e2 >> 12;
    int e = e2 & 4095;
    __shared__ float wigS[256];
    __shared__ float gS[16];
    __shared__ float red[64];
    int node  = eidx[half ? (NEDGE + e) : e];
    int other = eidx[half ? e : (NEDGE + e)];
    wigS[tid]       = wign[e * 256 + tid];
    wigS[tid + 128] = wign[e * 256 + 128 + tid];
    if (tid < 16) gS[tid] = glovec[other * LR + tid];
    __syncthreads();

    float xr[16];
    const float* xp = x + (size_t)node * XLC;
#pragma unroll
    for (int j = 0; j < 16; j++) xr[j] = xp[j * 128 + tid];

    int lane = tid & 31, warp = tid >> 5;
    float* fp = feat + (size_t)e2 * FEATW;
#pragma unroll
    for (int i = 0; i < 16; i++) {
        float a = 0.0f;
#pragma unroll
        for (int j = 0; j < 16; j++) a = fmaf(wigS[j * 16 + i], xr[j], a);
        fp[i * 129 + tid] = rtf(a);
        float s = a;
#pragma unroll
        for (int o = 16; o > 0; o >>= 1) s += __shfl_xor_sync(0xffffffffu, s, o);
        if (lane == 0) red[i * 4 + warp] = s;
    }
    __syncthreads();
    if (tid < 16) {
        float s = red[tid * 4] + red[tid * 4 + 1] + red[tid * 4 + 2] + red[tid * 4 + 3];
        fp[tid * 129 + 128] = rtf(s * (1.0f / 128.0f) * gS[tid]);
    }
}

// fused: sh compute (wig_node @ (h2a+h2b)) + z-build + wigner rotate
__global__ __launch_bounds__(256)
void k_rotmsg(const float* __restrict__ x, const int* __restrict__ eidx,
              const float* __restrict__ Aarr, const float* __restrict__ h2,
              const float* __restrict__ wign, const float* __restrict__ wigner,
              float* __restrict__ msg)
{
    int e = blockIdx.x, tid = threadIdx.x;
    __shared__ float zs[LF * 128];
    __shared__ float wgS[48 * 49];
    __shared__ float As_[LF];
    __shared__ float wigS[256];
    int src = eidx[e], dst = eidx[NEDGE + e];
    const float4* xs4 = (const float4*)(x + (size_t)src * XLC);
    const float4* xt4 = (const float4*)(x + (size_t)dst * XLC);
    wigS[tid] = wign[e * 256 + tid];          // 256 threads cover 256 entries
    if (tid < LF) As_[tid] = Aarr[e * LF + tid];
    __syncthreads();

    float4* zs4 = (float4*)zs;
    for (int i4 = tid; i4 < LF * 32; i4 += 256) {
        int l = i4 >> 5;
        float4 a = xs4[i4], b = xt4[i4];
        float al = As_[l];
        float4 v;
        v.x = 2.0f * (a.x + b.x) + al;
        v.y = 2.0f * (a.y + b.y) + al;
        v.z = 2.0f * (a.z + b.z) + al;
        v.w = 2.0f * (a.w + b.w) + al;
        zs4[i4] = v;
    }
    const float4* wp4 = (const float4*)(wigner + (size_t)e * (48 * 49));
    float4* wg4 = (float4*)wgS;
    for (int i4 = tid; i4 < 588; i4 += 256) wg4[i4] = wp4[i4];
    __syncthreads();

    // sh add: c = tid (first 128 threads), identical fma chain to old k_sh2
    if (tid < 128) {
        float hr[16];
        const float* hpa = h2 + (size_t)e * MSGW;
        const float* hpb = h2 + (size_t)(e + NEDGE) * MSGW;
#pragma unroll
        for (int j = 0; j < 16; j++) hr[j] = hpa[j * 128 + tid] + hpb[j * 128 + tid];
#pragma unroll
        for (int i = 0; i < 16; i++) {
            float s = 0.0f;
#pragma unroll
            for (int j = 0; j < 16; j++) s = fmaf(wigS[i * 16 + j], hr[j], s);
            zs[i * 128 + tid] += s;
        }
    }
    __syncthreads();

    int cg = tid & 63, grp = tid >> 6;
    float2 acc[12];
#pragma unroll
    for (int rr = 0; rr < 12; rr++) { acc[rr].x = 0.0f; acc[rr].y = 0.0f; }
    const float2* z2 = (const float2*)zs;
    for (int l = 0; l < LF; l++) {
        float2 zv = z2[l * 64 + cg];
#pragma unroll
        for (int rr = 0; rr < 12; rr++) {
            float w = wgS[(grp * 12 + rr) * LF + l];
            acc[rr].x = fmaf(w, zv.x, acc[rr].x);
            acc[rr].y = fmaf(w, zv.y, acc[rr].y);
        }
    }
    float* mp = msg + (size_t)e * (NYR * MSGW);
#pragma unroll
    for (int rr = 0; rr < 12; rr++) {
        int row = grp * 12 + rr;
        float2 o; o.x = rtf(acc[rr].x); o.y = rtf(acc[rr].y);
        ((float2*)(mp + row * 128))[cg] = o;
    }
}

__global__ __launch_bounds__(256)
void k_out(const float* __restrict__ m2, const float* __restrict__ winv,
           float* __restrict__ out)
{
    int e = blockIdx.x, tid = threadIdx.x;
    __shared__ float mmS[16 * 128];
    __shared__ float wvS[LF * 16];
    const float4* mp4 = (const float4*)(m2 + (size_t)e * (NYR * MSGW));
    float4* mm4 = (float4*)mmS;
    for (int i4 = tid; i4 < 512; i4 += 256) {
        float4 a = mp4[i4], b = mp4[i4 + 512], c = mp4[i4 + 1024];
        float4 v;
        v.x = (a.x + b.x + c.x) * (1.0f / 3.0f);
        v.y = (a.y + b.y + c.y) * (1.0f / 3.0f);
        v.z = (a.z + b.z + c.z) * (1.0f / 3.0f);
        v.w = (a.w + b.w + c.w) * (1.0f / 3.0f);
        mm4[i4] = v;
    }
    const float4* wp4 = (const float4*)(winv + (size_t)e * (LF * 16));
    float4* wv4 = (float4*)wvS;
    for (int i4 = tid; i4 < 196; i4 += 256) wv4[i4] = wp4[i4];
    __syncthreads();

    const float INV3 = 0.5773502691896258f;
    int cg = tid & 63, grp = tid >> 6;
    const float2* mm2 = (const float2*)mmS;
    float* op = out + (size_t)e * XLC;
    for (int b = grp; b < LF; b += 4) {
        float2 s; s.x = 0.0f; s.y = 0.0f;
#pragma unroll
        for (int r = 0; r < 16; r++) {
            float w = wvS[b * 16 + r];
            float2 mv = mm2[r * 64 + cg];
            s.x = fmaf(w, mv.x, s.x);
            s.y = fmaf(w, mv.y, s.y);
        }
        s.x *= INV3; s.y *= INV3;
        ((float2*)(op + b * 128))[cg] = s;
    }
}

// ---------------------------------------------------------------------------
extern "C" void kernel_launch(void* const* d_in, const int* in_sizes, int n_in,
                              void* d_out, int out_size)
{
    const float* x      = (const float*)d_in[0];
    const float* glovec = (const float*)d_in[2];
    const float* x_edge = (const float*)d_in[3];
    const int*   eidx   = (const int*)  d_in[4];
    const float* W_cg1  = (const float*)d_in[8];
    const float* W_cg21 = (const float*)d_in[9];
    const float* W_cg22 = (const float*)d_in[10];
    const float* Wn1a   = (const float*)d_in[11];
    const float* bn1a   = (const float*)d_in[12];
    const float* Wn1b   = (const float*)d_in[13];
    const float* bn1b   = (const float*)d_in[14];
    const float* Wn2a   = (const float*)d_in[15];
    const float* bn2a   = (const float*)d_in[16];
    const float* Wn2b   = (const float*)d_in[17];
    const float* bn2b   = (const float*)d_in[18];
    const float* Wd     = (const float*)d_in[19];
    const float* bd     = (const float*)d_in[20];
    const float* Wp1    = (const float*)d_in[21];
    const float* bp1    = (const float*)d_in[22];
    const float* Wp2    = (const float*)d_in[23];
    const float* bp2    = (const float*)d_in[24];
    const float* wigner = (const float*)d_in[25];
    const float* winv   = (const float*)d_in[26];
    const float* wign   = (const float*)d_in[27];
    float* out = (float*)d_out;

    float *pWdT, *pW1aT, *pW1bT, *pW2aT, *pW2bT, *pWp1T, *pWp2T, *pWc1T, *pWc2T, *pWc3T;
    float *p_xer, *p_xe, *p_nm, *p_xm, *p_ym, *p_t3, *p_A, *p_feat, *p_h, *p_h2,
          *p_msg, *p_m1, *p_m2, *p_part;
    cudaGetSymbolAddress((void**)&pWdT,  g_WdT);
    cudaGetSymbolAddress((void**)&pW1aT, g_Wn1aT);
    cudaGetSymbolAddress((void**)&pW1bT, g_Wn1bT);
    cudaGetSymbolAddress((void**)&pW2aT, g_Wn2aT);
    cudaGetSymbolAddress((void**)&pW2bT, g_Wn2bT);
    cudaGetSymbolAddress((void**)&pWp1T, g_Wp1T);
    cudaGetSymbolAddress((void**)&pWp2T, g_Wp2T);
    cudaGetSymbolAddress((void**)&pWc1T, g_Wc1T);
    cudaGetSymbolAddress((void**)&pWc2T, g_Wc2T);
    cudaGetSymbolAddress((void**)&pWc3T, g_Wc3T);
    cudaGetSymbolAddress((void**)&p_xer,  g_xer);
    cudaGetSymbolAddress((void**)&p_xe,   g_xe);
    cudaGetSymbolAddress((void**)&p_nm,   g_nm);
    cudaGetSymbolAddress((void**)&p_xm,   g_xm);
    cudaGetSymbolAddress((void**)&p_ym,   g_ym);
    cudaGetSymbolAddress((void**)&p_t3,   g_t3);
    cudaGetSymbolAddress((void**)&p_A,    g_A);
    cudaGetSymbolAddress((void**)&p_feat, g_feat);
    cudaGetSymbolAddress((void**)&p_h,    g_h);
    cudaGetSymbolAddress((void**)&p_h2,   g_h2);
    cudaGetSymbolAddress((void**)&p_msg,  g_msg);
    cudaGetSymbolAddress((void**)&p_m1,   g_m1);
    cudaGetSymbolAddress((void**)&p_m2,   g_m2);
    cudaGetSymbolAddress((void**)&p_part, g_part);

    cudaFuncSetAttribute(tgemm<0>, cudaFuncAttributeMaxDynamicSharedMemorySize, DYN_SMEM);
    cudaFuncSetAttribute(tgemm<1>, cudaFuncAttributeMaxDynamicSharedMemorySize, DYN_SMEM);
    cudaFuncSetAttribute(tgemm<2>, cudaFuncAttributeMaxDynamicSharedMemorySize, DYN_SMEM);

    const int BIG = 1 << 30;

    // ---- weight transposes (tf32-rounded) + x_edge rounding ----
    {
        TDPack P;
        auto set = [&](int i, const float* s, float* dst, int R, int C, int ldD, int& off) {
            int tx = (C + 31) / 32, ty = (ldD + 31) / 32;
            P.d[i] = TD{ s, dst, R, C, ldD, tx, off };
            off += tx * ty;
        };
        int off = 0;
        set(0, Wd,    pWdT,  128,  128,  128,  off);
        set(1, Wn1a,  pW1aT, FEATW,128,  FEATW,off);
        set(2, Wn1b,  pW1bT, 128,  2048, 128,  off);
        set(3, Wn2a,  pW2aT, FEATW,128,  FEATW,off);
        set(4, Wn2b,  pW2bT, 128,  2048, 128,  off);
        set(5, Wp1,   pWp1T, 2048, 128,  2048, off);
        set(6, Wp2,   pWp2T, 128,  2048, 128,  off);
        set(7, W_cg1, pWc1T, 49,   1225, KCG,  off);
        set(8, W_cg21,pWc2T, 49,   1225, KCG,  off);
        set(9, W_cg22,pWc3T, 49,   1225, KCG,  off);
        k_tmulti<<<off, 256>>>(P, 10);
    }
    k_round<<<(NEDGE * 128 + 255) / 256, 256>>>(x_edge, p_xer, NEDGE * 128);

    // 1. xe = silu(x_edge @ Wd + bd)
    tgemm<1><<<dim3(1, 32, 1), 128, DYN_SMEM>>>(
        p_xer, nullptr, nullptr, pWdT, nullptr, nullptr, bd, nullptr, nullptr,
        p_xe, NEDGE, 128, 128, 128, 4, 4, 0, BIG);

    // 2. per-node channel means, gathered to edges
    k_nodemean<<<NNODE, 128>>>(x, p_nm);
    k_gather<<<(NEDGE * KCG + 255) / 256, 256>>>(p_nm, eidx, p_xm, p_ym);

    // 3. CG bilinears: batched z=3, then fused mid+contract
    tgemm<0><<<dim3(10, 32, 3), 128, DYN_SMEM>>>(
        p_xm, p_xm, p_ym, pWc1T, pWc2T, pWc3T, nullptr, nullptr, nullptr,
        p_t3, NEDGE, 1225, KCG, TPAD, 2, 2, 1, BIG);
    k_midcon<<<NEDGE, 64>>>(p_ym, p_t3, p_t3 + (size_t)NEDGE * TPAD,
                            p_t3 + 2 * (size_t)NEDGE * TPAD, p_A);

    // 4+5. node_interactions batched
    k_feat<<<2 * NEDGE, 128>>>(x, glovec, wign, eidx, p_feat);
    tgemm<0><<<dim3(1, 64, 4), 128, DYN_SMEM>>>(
        p_feat, nullptr, nullptr, pW1aT, pW2aT, nullptr, nullptr, nullptr, nullptr,
        p_part, 2 * NEDGE, 128, FEATW, 128, 65, 17, 0, 32);
    k_combine<1><<<(2 * NEDGE * 128 + 255) / 256, 256>>>(
        p_part, bn1a, bn2a, nullptr, p_h, 2 * NEDGE, 4, NEDGE);
    tgemm<1><<<dim3(16, 64, 1), 128, DYN_SMEM>>>(
        p_h, nullptr, nullptr, pW1bT, pW2bT, nullptr, bn1b, bn2b, nullptr,
        p_h2, 2 * NEDGE, 2048, 128, 2048, 4, 4, 0, 32);

    // 6. fused sh + z-build + rotate (msg tf32-rounded for Wp1 GEMM)
    k_rotmsg<<<NEDGE, 256>>>(x, eidx, p_A, p_h2, wign, wigner, p_msg);

    // 7. edge MLP
    tgemm<0><<<dim3(1, 96, 2), 128, DYN_SMEM>>>(
        p_msg, nullptr, nullptr, pWp1T, nullptr, nullptr, nullptr, nullptr, nullptr,
        p_part, NEDGE * NYR, 128, 2048, 128, 64, 32, 0, BIG);
    k_combine<2><<<(NEDGE * NYR * 128 + 255) / 256, 256>>>(
        p_part, bp1, bp1, p_xe, p_m1, NEDGE * NYR, 2, BIG);
    tgemm<1><<<dim3(16, 96, 1), 128, DYN_SMEM>>>(
        p_m1, nullptr, nullptr, pWp2T, nullptr, nullptr, bp2, nullptr, nullptr,
        p_m2, NEDGE * NYR, 2048, 128, 2048, 4, 4, 0, BIG);

    // 8. NY-mean + inverse rotation
    k_out<<<NEDGE, 256>>>(p_m2, winv, out);
}